// round 5
// baseline (speedup 1.0000x reference)
#include <cuda_runtime.h>
#include <cstdint>

// Problem constants (fixed by reference)
#define NN   100000
#define EE   1600000
#define FH   128      // F_IN == H == HG
#define H3   384      // 3*HG
#define CC   40
#define LL   3

// ---------------- scratch (device globals; no allocation allowed) ----------
__device__ float g_xh[(size_t)NN * FH];
__device__ float g_xw[(size_t)NN * FH];
__device__ float g_h [(size_t)NN * FH];
__device__ float g_gi[(size_t)NN * H3];   // first NN*FH also reused as agg
__device__ float g_gh[(size_t)NN * H3];
__device__ float g_deg [NN];
__device__ float g_dinv[NN];

// ---------------- degree / normalization ----------------
__global__ void init_deg_kernel() {
    int i = blockIdx.x * blockDim.x + threadIdx.x;
    if (i < NN) g_deg[i] = 1.0f;   // self-loop weight 1
}

__global__ void accum_deg_kernel(const int* __restrict__ dst,
                                 const float* __restrict__ ew) {
    int e = blockIdx.x * blockDim.x + threadIdx.x;
    if (e < EE) atomicAdd(&g_deg[dst[e]], ew[e]);
}

__global__ void dinv_kernel() {
    int i = blockIdx.x * blockDim.x + threadIdx.x;
    if (i < NN) g_dinv[i] = rsqrtf(g_deg[i]);   // deg >= 1 always
}

// =====================================================================
// TF32 tensor-core GEMM v3: C[M,Ncols] = A[M,128] * B (+bias)(+relu)
//   TRANSB=false: B is [128, Ncols] row-major
//   TRANSB=true : B is [Ncols, 128] row-major (C = A * B^T)
//   SELF=true  : additionally write agg[r] = C[r]*dinv[r]^2 (Ncols==128 only)
// CTA tile 128x128, K=128 fully resident in smem as PRE-SWIZZLED MMA
// fragments, filled via COALESCED float4 gmem reads + scalar smem writes.
// 512 threads / 16 warps, warp tile 32x32, mma.m16n8k8.tf32.
//   AsF: float4[128*32]  (frag = tm*16+ks, elem = lane)   64KB
//   BsF: float2[256*32]  (frag = tn*16+ks, elem = lane)   64KB
// =====================================================================
#define GEMM_SMEM_BYTES (128 * 1024)

__device__ __forceinline__ float to_tf32(float v) {
    uint32_t o;
    asm volatile("cvt.rna.tf32.f32 %0, %1;" : "=r"(o) : "f"(v));
    return __uint_as_float(o);
}

__device__ __forceinline__ void mma_tf32(float* d, const float4& a,
                                         const float2& b) {
    asm volatile(
        "mma.sync.aligned.m16n8k8.row.col.f32.tf32.tf32.f32 "
        "{%0,%1,%2,%3}, {%4,%5,%6,%7}, {%8,%9}, {%0,%1,%2,%3};\n"
        : "+f"(d[0]), "+f"(d[1]), "+f"(d[2]), "+f"(d[3])
        : "r"(__float_as_uint(a.x)), "r"(__float_as_uint(a.y)),
          "r"(__float_as_uint(a.z)), "r"(__float_as_uint(a.w)),
          "r"(__float_as_uint(b.x)), "r"(__float_as_uint(b.y)));
}

template<bool TRANSB, bool BIAS, bool RELU, bool SELF>
__global__ __launch_bounds__(512, 1)
void gemm_tf32_kernel(const float* __restrict__ A,
                      const float* __restrict__ B,
                      const float* __restrict__ bias,
                      float* __restrict__ C,
                      float* __restrict__ agg,
                      int M, int Ncols) {
    extern __shared__ float4 smem4[];
    float4* AsF = smem4;                       // [128*32] float4
    float2* BsF = (float2*)(smem4 + 128 * 32); // [256*32] float2
    float*  AsS = (float*)AsF;
    float*  BsS = (float*)BsF;

    const int tid  = threadIdx.x;
    const int lane = tid & 31;
    const int wid  = tid >> 5;                 // 0..15
    const int lr   = lane >> 2;                // 0..7
    const int lc   = lane & 3;                 // 0..3
    const int bm = blockIdx.y * 128;
    const int bn = blockIdx.x * 128;

    // ---- fill A fragments: coalesced float4 reads, scalar frag writes ----
    // float4 A[m][4q..4q+3] -> frag (m>>4, q>>1), comp (q&1)*2+((m&15)>>3),
    //                          lanes (m&7)*4 + j
    #pragma unroll
    for (int it = 0; it < 8; it++) {
        int i = it * 512 + tid;         // 4096 float4 slots
        int m = i >> 5;                 // 0..127
        int q = i & 31;
        int gr = bm + m;
        float4 v = make_float4(0.f, 0.f, 0.f, 0.f);
        if (gr < M) v = *(const float4*)(A + (size_t)gr * 128 + (q << 2));
        int tm = m >> 4, rr = m & 15;
        int flr = rr & 7, hi = rr >> 3;
        int ks = q >> 1, half = q & 1;
        int comp = half * 2 + hi;
        int base = ((tm * 16 + ks) * 32 + flr * 4);
        AsS[(base + 0) * 4 + comp] = to_tf32(v.x);
        AsS[(base + 1) * 4 + comp] = to_tf32(v.y);
        AsS[(base + 2) * 4 + comp] = to_tf32(v.z);
        AsS[(base + 3) * 4 + comp] = to_tf32(v.w);
    }
    // ---- fill B fragments ----
    if (TRANSB) {
        // float4 B[bn+n][4q..4q+3] -> frag (n>>3, q>>1), comp q&1,
        //                            lanes (n&7)*4 + j
        #pragma unroll
        for (int it = 0; it < 8; it++) {
            int i = it * 512 + tid;
            int n = i >> 5;             // 0..127
            int q = i & 31;
            float4 v = *(const float4*)(B + (size_t)(bn + n) * 128 + (q << 2));
            int tn = n >> 3, flr = n & 7;
            int ks = q >> 1, half = q & 1;
            int base = ((tn * 16 + ks) * 32 + flr * 4);
            BsS[(base + 0) * 2 + half] = to_tf32(v.x);
            BsS[(base + 1) * 2 + half] = to_tf32(v.y);
            BsS[(base + 2) * 2 + half] = to_tf32(v.z);
            BsS[(base + 3) * 2 + half] = to_tf32(v.w);
        }
    } else {
        // float4 B[k][bn+4p..4p+3] -> frag (p>>1, k>>3), comp (k>>2)&1,
        //                             lanes ((p&1)*4+j)*4 + (k&3)
        #pragma unroll
        for (int it = 0; it < 8; it++) {
            int i = it * 512 + tid;
            int k = i >> 5;             // 0..127
            int p = i & 31;
            float4 v = *(const float4*)(B + (size_t)k * Ncols + bn + (p << 2));
            int tn = p >> 1;
            int ks = k >> 3, lc3 = k & 3, half = (k >> 2) & 1;
            int lrb = (p & 1) * 4;
            int fb = (tn * 16 + ks) * 32;
            BsS[(fb + (lrb + 0) * 4 + lc3) * 2 + half] = to_tf32(v.x);
            BsS[(fb + (lrb + 1) * 4 + lc3) * 2 + half] = to_tf32(v.y);
            BsS[(fb + (lrb + 2) * 4 + lc3) * 2 + half] = to_tf32(v.z);
            BsS[(fb + (lrb + 3) * 4 + lc3) * 2 + half] = to_tf32(v.w);
        }
    }
    __syncthreads();

    // warp tile: 32 rows x 32 cols; warp grid 4x4
    const int wtm = wid & 3;       // m-warp 0..3
    const int wtn = wid >> 2;      // n-warp 0..3

    float acc[2][4][4];
    #pragma unroll
    for (int mi = 0; mi < 2; mi++)
        #pragma unroll
        for (int ni = 0; ni < 4; ni++)
            #pragma unroll
            for (int j = 0; j < 4; j++) acc[mi][ni][j] = 0.f;

    const float4* ap0 = AsF + ((wtm * 2 + 0) * 16) * 32 + lane;
    const float4* ap1 = AsF + ((wtm * 2 + 1) * 16) * 32 + lane;
    const float2* bp0 = BsF + ((wtn * 4 + 0) * 16) * 32 + lane;
    const float2* bp1 = BsF + ((wtn * 4 + 1) * 16) * 32 + lane;
    const float2* bp2 = BsF + ((wtn * 4 + 2) * 16) * 32 + lane;
    const float2* bp3 = BsF + ((wtn * 4 + 3) * 16) * 32 + lane;

    #pragma unroll
    for (int ks = 0; ks < 16; ks++) {
        float4 a0 = ap0[ks * 32];
        float4 a1 = ap1[ks * 32];
        float2 b0 = bp0[ks * 32];
        float2 b1 = bp1[ks * 32];
        float2 b2 = bp2[ks * 32];
        float2 b3 = bp3[ks * 32];
        mma_tf32(acc[0][0], a0, b0); mma_tf32(acc[0][1], a0, b1);
        mma_tf32(acc[0][2], a0, b2); mma_tf32(acc[0][3], a0, b3);
        mma_tf32(acc[1][0], a1, b0); mma_tf32(acc[1][1], a1, b1);
        mma_tf32(acc[1][2], a1, b2); mma_tf32(acc[1][3], a1, b3);
    }

    // ---- epilogue ----
    #pragma unroll
    for (int mi = 0; mi < 2; mi++) {
        int r0 = bm + wtm * 32 + mi * 16 + lr;
        int r1 = r0 + 8;
        float di0 = 0.f, di1 = 0.f;
        if (SELF) {
            if (r0 < M) di0 = g_dinv[r0];
            if (r1 < M) di1 = g_dinv[r1];
        }
        #pragma unroll
        for (int ni = 0; ni < 4; ni++) {
            int c0 = bn + wtn * 32 + ni * 8 + (lc << 1);
            float b0 = 0.f, b1 = 0.f;
            if (BIAS) { b0 = bias[c0]; b1 = bias[c0 + 1]; }
            float v0 = acc[mi][ni][0] + b0;
            float v1 = acc[mi][ni][1] + b1;
            float v2 = acc[mi][ni][2] + b0;
            float v3 = acc[mi][ni][3] + b1;
            if (RELU) {
                v0 = fmaxf(v0, 0.f); v1 = fmaxf(v1, 0.f);
                v2 = fmaxf(v2, 0.f); v3 = fmaxf(v3, 0.f);
            }
            if (r0 < M) {
                *(float2*)(C + (size_t)r0 * Ncols + c0) = make_float2(v0, v1);
                if (SELF)
                    *(float2*)(agg + (size_t)r0 * 128 + c0) =
                        make_float2(v0 * di0 * di0, v1 * di0 * di0);
            }
            if (r1 < M) {
                *(float2*)(C + (size_t)r1 * Ncols + c0) = make_float2(v2, v3);
                if (SELF)
                    *(float2*)(agg + (size_t)r1 * 128 + c0) =
                        make_float2(v2 * di1 * di1, v3 * di1 * di1);
            }
        }
    }
}

// ---------------- fp32 fallback GEMM (used for fc, Ncols=40) --------------
__global__ void gemm_fc_kernel(const float* __restrict__ A,
                               const float* __restrict__ B,
                               const float* __restrict__ bias,
                               float* __restrict__ C,
                               int M, int Ncols) {
    constexpr int K  = 128;
    constexpr int BM = 64, BN = 64, BK = 16;
    __shared__ float As[BK][BM + 4];
    __shared__ float Bs[BK][BN + 4];

    const int tid = threadIdx.x;
    const int bm = blockIdx.y * BM;
    const int bn = blockIdx.x * BN;
    const int tx = tid & 15;
    const int ty = tid >> 4;

    float acc[4][4] = {};

    for (int k0 = 0; k0 < K; k0 += BK) {
        {
            const int arow = tid >> 2;
            const int acol = (tid & 3) << 2;
            float4 av = make_float4(0.f, 0.f, 0.f, 0.f);
            const int gr = bm + arow;
            if (gr < M)
                av = *(const float4*)(A + (size_t)gr * K + k0 + acol);
            As[acol + 0][arow] = av.x;
            As[acol + 1][arow] = av.y;
            As[acol + 2][arow] = av.z;
            As[acol + 3][arow] = av.w;
        }
        {
            const int brow = tid >> 4;
            const int bcol = (tid & 15) << 2;
            const int gc = bn + bcol;
            Bs[brow][bcol + 0] = (gc + 0 < Ncols) ? B[(size_t)(k0 + brow) * Ncols + gc + 0] : 0.f;
            Bs[brow][bcol + 1] = (gc + 1 < Ncols) ? B[(size_t)(k0 + brow) * Ncols + gc + 1] : 0.f;
            Bs[brow][bcol + 2] = (gc + 2 < Ncols) ? B[(size_t)(k0 + brow) * Ncols + gc + 2] : 0.f;
            Bs[brow][bcol + 3] = (gc + 3 < Ncols) ? B[(size_t)(k0 + brow) * Ncols + gc + 3] : 0.f;
        }
        __syncthreads();

        #pragma unroll
        for (int k = 0; k < BK; k++) {
            float4 a = *(const float4*)(&As[k][ty << 2]);
            float4 b = *(const float4*)(&Bs[k][tx << 2]);
            acc[0][0] += a.x * b.x; acc[0][1] += a.x * b.y;
            acc[0][2] += a.x * b.z; acc[0][3] += a.x * b.w;
            acc[1][0] += a.y * b.x; acc[1][1] += a.y * b.y;
            acc[1][2] += a.y * b.z; acc[1][3] += a.y * b.w;
            acc[2][0] += a.z * b.x; acc[2][1] += a.z * b.y;
            acc[2][2] += a.z * b.z; acc[2][3] += a.z * b.w;
            acc[3][0] += a.w * b.x; acc[3][1] += a.w * b.y;
            acc[3][2] += a.w * b.z; acc[3][3] += a.w * b.w;
        }
        __syncthreads();
    }

    float bv[4] = {0.f, 0.f, 0.f, 0.f};
    #pragma unroll
    for (int j = 0; j < 4; j++) {
        int c = bn + (tx << 2) + j;
        bv[j] = (c < Ncols) ? bias[c] : 0.f;
    }
    #pragma unroll
    for (int i = 0; i < 4; i++) {
        int r = bm + (ty << 2) + i;
        if (r >= M) continue;
        #pragma unroll
        for (int j = 0; j < 4; j++) {
            int c = bn + (tx << 2) + j;
            if (c >= Ncols) continue;
            C[(size_t)r * Ncols + c] = acc[i][j] + bv[j];
        }
    }
}

// ---------------- edge scatter: one warp per edge ----------------
__global__ void scatter_kernel(const int* __restrict__ src,
                               const int* __restrict__ dst,
                               const float* __restrict__ ew,
                               const float* __restrict__ xw,
                               float* __restrict__ agg) {
    int warp = (blockIdx.x * blockDim.x + threadIdx.x) >> 5;
    int lane = threadIdx.x & 31;
    if (warp >= EE) return;
    int s = src[warp];
    int d = dst[warp];
    float norm = g_dinv[s] * ew[warp] * g_dinv[d];
    float4 v = ((const float4*)(xw + (size_t)s * FH))[lane];
    float* base = agg + (size_t)d * FH + (lane << 2);
    atomicAdd(base + 0, v.x * norm);
    atomicAdd(base + 1, v.y * norm);
    atomicAdd(base + 2, v.z * norm);
    atomicAdd(base + 3, v.w * norm);
}

// ---------------- bias + relu: xh = relu(agg + b) ----------------
__global__ void bias_relu_kernel(const float* __restrict__ agg,
                                 float* __restrict__ xh,
                                 const float* __restrict__ b) {
    size_t idx = (size_t)blockIdx.x * blockDim.x + threadIdx.x;
    if (idx >= (size_t)NN * FH) return;
    int f = (int)(idx & (FH - 1));
    xh[idx] = fmaxf(agg[idx] + b[f], 0.f);
}

// ---------------- GRU elementwise ----------------
__global__ void gru_kernel(const float* __restrict__ gi,
                           const float* __restrict__ gh,
                           const float* __restrict__ hprev,
                           float* __restrict__ hout) {
    size_t idx = (size_t)blockIdx.x * blockDim.x + threadIdx.x;
    if (idx >= (size_t)NN * FH) return;
    int n = (int)(idx >> 7);
    int j = (int)(idx & (FH - 1));
    size_t base = (size_t)n * H3 + j;
    float ir = gi[base          ];
    float iz = gi[base + FH     ];
    float in_ = gi[base + 2 * FH];
    float hr = gh[base          ];
    float hz = gh[base + FH     ];
    float hn = gh[base + 2 * FH];
    float hv = hprev[idx];
    float r = 1.f / (1.f + expf(-(ir + hr)));
    float z = 1.f / (1.f + expf(-(iz + hz)));
    float nn = tanhf(in_ + r * hn);
    hout[idx] = (1.f - z) * nn + z * hv;
}

// ---------------- host orchestration ----------------
extern "C" void kernel_launch(void* const* d_in, const int* in_sizes, int n_in,
                              void* d_out, int out_size) {
    const float* x     = (const float*)d_in[0];
    const int*   ei    = (const int*)  d_in[1];
    const float* ew    = (const float*)d_in[2];
    const float* h0    = (const float*)d_in[3];
    const float* linW  = (const float*)d_in[4];
    const float* linB  = (const float*)d_in[5];
    const float* convW = (const float*)d_in[6];
    const float* convB = (const float*)d_in[7];
    const float* Wih   = (const float*)d_in[8];
    const float* Whh   = (const float*)d_in[9];
    const float* bih   = (const float*)d_in[10];
    const float* bhh   = (const float*)d_in[11];
    const float* fcW   = (const float*)d_in[12];
    const float* fcB   = (const float*)d_in[13];
    float* out = (float*)d_out;

    const int* src = ei;
    const int* dst = ei + EE;

    // one-time: allow >48KB dynamic smem for tf32 instantiations
    static bool s_attr_done = false;
    if (!s_attr_done) {
        cudaFuncSetAttribute(gemm_tf32_kernel<false, true, true, false>,
                             cudaFuncAttributeMaxDynamicSharedMemorySize, GEMM_SMEM_BYTES);
        cudaFuncSetAttribute(gemm_tf32_kernel<true, true, false, false>,
                             cudaFuncAttributeMaxDynamicSharedMemorySize, GEMM_SMEM_BYTES);
        cudaFuncSetAttribute(gemm_tf32_kernel<false, false, false, true>,
                             cudaFuncAttributeMaxDynamicSharedMemorySize, GEMM_SMEM_BYTES);
        s_attr_done = true;
    }

    // scratch symbol addresses (not stream ops; graph-capture safe)
    float *p_xh, *p_xw, *p_h, *p_gi, *p_gh;
    cudaGetSymbolAddress((void**)&p_xh, g_xh);
    cudaGetSymbolAddress((void**)&p_xw, g_xw);
    cudaGetSymbolAddress((void**)&p_h,  g_h);
    cudaGetSymbolAddress((void**)&p_gi, g_gi);
    cudaGetSymbolAddress((void**)&p_gh, g_gh);
    float* p_agg = p_gi;   // reuse gi's first NN*FH floats as agg scratch

    const size_t NF = (size_t)NN * FH;
    const int EB = 256;

    const dim3 blk512(512);
    const dim3 grid128(1, (NN + 127) / 128);     // Ncols=128
    const dim3 grid384(3, (NN + 127) / 128);     // Ncols=384
    const size_t sm = GEMM_SMEM_BYTES;

    // degree + normalization
    init_deg_kernel<<<(NN + 255) / 256, 256>>>();
    accum_deg_kernel<<<(EE + EB - 1) / EB, EB>>>(dst, ew);
    dinv_kernel<<<(NN + 255) / 256, 256>>>();

    // xh = relu(x @ linW + linB)
    gemm_tf32_kernel<false, true, true, false><<<grid128, blk512, sm>>>(
        x, linW, linB, p_xh, nullptr, NN, FH);

    // h = GRU(xh, h0)
    gemm_tf32_kernel<true, true, false, false><<<grid384, blk512, sm>>>(
        p_xh, Wih, bih, p_gi, nullptr, NN, H3);
    gemm_tf32_kernel<true, true, false, false><<<grid384, blk512, sm>>>(
        h0, Whh, bhh, p_gh, nullptr, NN, H3);
    gru_kernel<<<(int)((NF + 255) / 256), 256>>>(p_gi, p_gh, h0, p_h);

    for (int l = 0; l < LL; l++) {
        const float* W = convW + (size_t)l * FH * FH;
        const float* b = convB + (size_t)l * FH;
        // xw = xh @ W ; agg = xw * dinv^2 (fused self-loop init)
        gemm_tf32_kernel<false, false, false, true><<<grid128, blk512, sm>>>(
            p_xh, W, nullptr, p_xw, p_agg, NN, FH);
        // edge scatter into agg
        scatter_kernel<<<(EE * 32 + 255) / 256, 256>>>(src, dst, ew, p_xw, p_agg);
        // xh = relu(agg + b)
        bias_relu_kernel<<<(int)((NF + 255) / 256), 256>>>(p_agg, p_xh, b);
        // h = GRU(xh, h)
        gemm_tf32_kernel<true, true, false, false><<<grid384, blk512, sm>>>(
            p_xh, Wih, bih, p_gi, nullptr, NN, H3);
        gemm_tf32_kernel<true, true, false, false><<<grid384, blk512, sm>>>(
            p_h, Whh, bhh, p_gh, nullptr, NN, H3);
        gru_kernel<<<(int)((NF + 255) / 256), 256>>>(p_gi, p_gh, p_h, p_h);
    }

    // out = h @ fcW + fcB (fp32 fallback: Ncols=40)
    {
        dim3 grid((CC + 63) / 64, (NN + 63) / 64);
        gemm_fc_kernel<<<grid, 256>>>(p_h, fcW, fcB, out, NN, CC);
    }
}

// round 8
// speedup vs baseline: 1.8676x; 1.8676x over previous
#include <cuda_runtime.h>
#include <cstdint>

// Problem constants (fixed by reference)
#define NN   100000
#define EE   1600000
#define FH   128      // F_IN == H == HG
#define H3   384      // 3*HG
#define CC   40
#define LL   3

// ---------------- scratch (device globals; no allocation allowed) ----------
__device__ float g_xh[(size_t)NN * FH];
__device__ float g_xw[(size_t)NN * FH];
__device__ float g_h [(size_t)NN * FH];
__device__ float g_gi[(size_t)NN * H3];   // first NN*FH also reused as agg
__device__ float g_gh[(size_t)NN * H3];
__device__ float g_deg [NN];
__device__ float g_dinv[NN];

// ---------------- degree / normalization ----------------
__global__ void init_deg_kernel() {
    int i = blockIdx.x * blockDim.x + threadIdx.x;
    if (i < NN) g_deg[i] = 1.0f;   // self-loop weight 1
}

__global__ void accum_deg_kernel(const int* __restrict__ dst,
                                 const float* __restrict__ ew) {
    int e = blockIdx.x * blockDim.x + threadIdx.x;
    if (e < EE) atomicAdd(&g_deg[dst[e]], ew[e]);
}

__global__ void dinv_kernel() {
    int i = blockIdx.x * blockDim.x + threadIdx.x;
    if (i < NN) g_dinv[i] = rsqrtf(g_deg[i]);   // deg >= 1 always
}

// =====================================================================
// TF32 tensor-core GEMM v4: C[M,Ncols] = A[M,128] * B (+bias)(+relu)
//   TRANSB=false: B is [128, Ncols] row-major
//   TRANSB=true : B is [Ncols, 128] row-major (C = A * B^T)
//   SELF=true  : additionally write agg[r] = C[r]*dinv[r]^2 (Ncols==128 only)
// CTA tile 128x128, K=128 fully resident in smem, ROW-MAJOR PADDED layout
// (As[m][k], Bs[n][k], stride TS=132 -> conflict-free float4 fills AND
// conflict-free ldmatrix). Fragments loaded via ldmatrix.m8n8.x4.b16
// (8x8 b16 == 8x4 tf32; x4 mapping == tf32 m16n8k8 fragment exactly).
// 512 threads / 16 warps, warp tile 32x32.
// =====================================================================
#define TS 132
#define GEMM_SMEM_BYTES (2 * 128 * TS * 4)   // 135168 B

__device__ __forceinline__ float to_tf32(float v) {
    uint32_t o;
    asm volatile("cvt.rna.tf32.f32 %0, %1;" : "=r"(o) : "f"(v));
    return __uint_as_float(o);
}

__device__ __forceinline__ void ldsm4(uint32_t* r, uint32_t addr) {
    asm volatile(
        "ldmatrix.sync.aligned.m8n8.x4.shared.b16 {%0,%1,%2,%3}, [%4];"
        : "=r"(r[0]), "=r"(r[1]), "=r"(r[2]), "=r"(r[3]) : "r"(addr));
}

__device__ __forceinline__ void mma_tf32(float* d, const uint32_t* a,
                                         uint32_t b0, uint32_t b1) {
    asm volatile(
        "mma.sync.aligned.m16n8k8.row.col.f32.tf32.tf32.f32 "
        "{%0,%1,%2,%3}, {%4,%5,%6,%7}, {%8,%9}, {%0,%1,%2,%3};\n"
        : "+f"(d[0]), "+f"(d[1]), "+f"(d[2]), "+f"(d[3])
        : "r"(a[0]), "r"(a[1]), "r"(a[2]), "r"(a[3]), "r"(b0), "r"(b1));
}

template<bool TRANSB, bool BIAS, bool RELU, bool SELF>
__global__ __launch_bounds__(512, 1)
void gemm_tf32_kernel(const float* __restrict__ A,
                      const float* __restrict__ B,
                      const float* __restrict__ bias,
                      float* __restrict__ C,
                      float* __restrict__ agg,
                      int M, int Ncols) {
    extern __shared__ float smem[];
    float* As = smem;             // [128][TS]
    float* Bs = smem + 128 * TS;  // [128][TS]

    const int tid  = threadIdx.x;
    const int lane = tid & 31;
    const int wid  = tid >> 5;                 // 0..15
    const int lr   = lane >> 2;                // 0..7
    const int lc   = lane & 3;                 // 0..3
    const int bm = blockIdx.y * 128;
    const int bn = blockIdx.x * 128;

    // ---- fill As[m][k]: each warp fills one row per iter (coalesced,
    //      STS.128 conflict-free: 32 consecutive 16B within a 528B row) ----
    #pragma unroll
    for (int it = 0; it < 8; it++) {
        int i = it * 512 + tid;         // 4096 float4 slots
        int m = i >> 5;
        int q = (i & 31) << 2;
        int gr = bm + m;
        float4 v = make_float4(0.f, 0.f, 0.f, 0.f);
        if (gr < M) v = *(const float4*)(A + (size_t)gr * 128 + q);
        float4 w = make_float4(to_tf32(v.x), to_tf32(v.y),
                               to_tf32(v.z), to_tf32(v.w));
        *(float4*)(As + m * TS + q) = w;
    }
    // ---- fill Bs[n][k] ----
    if (TRANSB) {
        #pragma unroll
        for (int it = 0; it < 8; it++) {
            int i = it * 512 + tid;
            int n = i >> 5;
            int q = (i & 31) << 2;
            float4 v = *(const float4*)(B + (size_t)(bn + n) * 128 + q);
            float4 w = make_float4(to_tf32(v.x), to_tf32(v.y),
                                   to_tf32(v.z), to_tf32(v.w));
            *(float4*)(Bs + n * TS + q) = w;
        }
    } else {
        // transpose fill: Bs[n][k] = B[k][bn+n]; coalesced gmem reads,
        // scalar smem stores (small shared weight matrix, amortized)
        #pragma unroll
        for (int it = 0; it < 8; it++) {
            int i = it * 512 + tid;
            int k = i >> 5;
            int p = (i & 31) << 2;
            float4 v = *(const float4*)(B + (size_t)k * Ncols + bn + p);
            Bs[(p + 0) * TS + k] = to_tf32(v.x);
            Bs[(p + 1) * TS + k] = to_tf32(v.y);
            Bs[(p + 2) * TS + k] = to_tf32(v.z);
            Bs[(p + 3) * TS + k] = to_tf32(v.w);
        }
    }
    __syncthreads();

    // warp tile: 32 rows x 32 cols; warp grid 4x4
    const int wtm = wid & 3;       // m-warp 0..3
    const int wtn = wid >> 2;      // n-warp 0..3

    // per-lane ldmatrix base addresses (byte smem addresses)
    // A tile mi: lanes 0-7 -> m0 (rows +0..7, k+0), 8-15 -> m1 (rows +8..15,
    // k+0), 16-23 -> m2 (rows +0..7, k+4), 24-31 -> m3 (rows +8..15, k+4)
    uint32_t as_base = (uint32_t)__cvta_generic_to_shared(As);
    uint32_t bs_base = (uint32_t)__cvta_generic_to_shared(Bs);
    int arow = (lane & 7) + ((lane >> 3) & 1) * 8;
    int acol = (lane >> 4) << 2;
    uint32_t aAddr0 = as_base + (((wtm * 32 +  0 + arow) * TS + acol) << 2);
    uint32_t aAddr1 = as_base + (((wtm * 32 + 16 + arow) * TS + acol) << 2);
    // B pair p: lanes 0-7 -> rows +0..7 k+0 (b0 of ni=2p), 8-15 -> rows
    // +0..7 k+4 (b1 of ni=2p), 16-23 -> rows +8..15 k+0 (b0 of ni=2p+1),
    // 24-31 -> rows +8..15 k+4 (b1 of ni=2p+1)
    int brow = (lane & 7) + ((lane >> 4) << 3);
    int bcol = ((lane >> 3) & 1) << 2;
    uint32_t bAddr0 = bs_base + (((wtn * 32 +  0 + brow) * TS + bcol) << 2);
    uint32_t bAddr1 = bs_base + (((wtn * 32 + 16 + brow) * TS + bcol) << 2);

    float acc[2][4][4];
    #pragma unroll
    for (int mi = 0; mi < 2; mi++)
        #pragma unroll
        for (int ni = 0; ni < 4; ni++)
            #pragma unroll
            for (int j = 0; j < 4; j++) acc[mi][ni][j] = 0.f;

    #pragma unroll
    for (int ks = 0; ks < 16; ks++) {
        uint32_t a0[4], a1[4], b01[4], b23[4];
        uint32_t koff = ks * 32;    // 8 floats per k-step
        ldsm4(a0,  aAddr0 + koff);
        ldsm4(a1,  aAddr1 + koff);
        ldsm4(b01, bAddr0 + koff);
        ldsm4(b23, bAddr1 + koff);
        mma_tf32(acc[0][0], a0, b01[0], b01[1]);
        mma_tf32(acc[0][1], a0, b01[2], b01[3]);
        mma_tf32(acc[0][2], a0, b23[0], b23[1]);
        mma_tf32(acc[0][3], a0, b23[2], b23[3]);
        mma_tf32(acc[1][0], a1, b01[0], b01[1]);
        mma_tf32(acc[1][1], a1, b01[2], b01[3]);
        mma_tf32(acc[1][2], a1, b23[0], b23[1]);
        mma_tf32(acc[1][3], a1, b23[2], b23[3]);
    }

    // ---- epilogue ----
    #pragma unroll
    for (int mi = 0; mi < 2; mi++) {
        int r0 = bm + wtm * 32 + mi * 16 + lr;
        int r1 = r0 + 8;
        float di0 = 0.f, di1 = 0.f;
        if (SELF) {
            if (r0 < M) di0 = g_dinv[r0];
            if (r1 < M) di1 = g_dinv[r1];
        }
        #pragma unroll
        for (int ni = 0; ni < 4; ni++) {
            int c0 = bn + wtn * 32 + ni * 8 + (lc << 1);
            float b0 = 0.f, b1 = 0.f;
            if (BIAS) { b0 = bias[c0]; b1 = bias[c0 + 1]; }
            float v0 = acc[mi][ni][0] + b0;
            float v1 = acc[mi][ni][1] + b1;
            float v2 = acc[mi][ni][2] + b0;
            float v3 = acc[mi][ni][3] + b1;
            if (RELU) {
                v0 = fmaxf(v0, 0.f); v1 = fmaxf(v1, 0.f);
                v2 = fmaxf(v2, 0.f); v3 = fmaxf(v3, 0.f);
            }
            if (r0 < M) {
                *(float2*)(C + (size_t)r0 * Ncols + c0) = make_float2(v0, v1);
                if (SELF)
                    *(float2*)(agg + (size_t)r0 * 128 + c0) =
                        make_float2(v0 * di0 * di0, v1 * di0 * di0);
            }
            if (r1 < M) {
                *(float2*)(C + (size_t)r1 * Ncols + c0) = make_float2(v2, v3);
                if (SELF)
                    *(float2*)(agg + (size_t)r1 * 128 + c0) =
                        make_float2(v2 * di1 * di1, v3 * di1 * di1);
            }
        }
    }
}

// ---------------- fp32 fallback GEMM (used for fc, Ncols=40) --------------
__global__ void gemm_fc_kernel(const float* __restrict__ A,
                               const float* __restrict__ B,
                               const float* __restrict__ bias,
                               float* __restrict__ C,
                               int M, int Ncols) {
    constexpr int K  = 128;
    constexpr int BM = 64, BN = 64, BK = 16;
    __shared__ float As[BK][BM + 4];
    __shared__ float Bs[BK][BN + 4];

    const int tid = threadIdx.x;
    const int bm = blockIdx.y * BM;
    const int bn = blockIdx.x * BN;
    const int tx = tid & 15;
    const int ty = tid >> 4;

    float acc[4][4] = {};

    for (int k0 = 0; k0 < K; k0 += BK) {
        {
            const int arow = tid >> 2;
            const int acol = (tid & 3) << 2;
            float4 av = make_float4(0.f, 0.f, 0.f, 0.f);
            const int gr = bm + arow;
            if (gr < M)
                av = *(const float4*)(A + (size_t)gr * K + k0 + acol);
            As[acol + 0][arow] = av.x;
            As[acol + 1][arow] = av.y;
            As[acol + 2][arow] = av.z;
            As[acol + 3][arow] = av.w;
        }
        {
            const int brow = tid >> 4;
            const int bcol = (tid & 15) << 2;
            const int gc = bn + bcol;
            Bs[brow][bcol + 0] = (gc + 0 < Ncols) ? B[(size_t)(k0 + brow) * Ncols + gc + 0] : 0.f;
            Bs[brow][bcol + 1] = (gc + 1 < Ncols) ? B[(size_t)(k0 + brow) * Ncols + gc + 1] : 0.f;
            Bs[brow][bcol + 2] = (gc + 2 < Ncols) ? B[(size_t)(k0 + brow) * Ncols + gc + 2] : 0.f;
            Bs[brow][bcol + 3] = (gc + 3 < Ncols) ? B[(size_t)(k0 + brow) * Ncols + gc + 3] : 0.f;
        }
        __syncthreads();

        #pragma unroll
        for (int k = 0; k < BK; k++) {
            float4 a = *(const float4*)(&As[k][ty << 2]);
            float4 b = *(const float4*)(&Bs[k][tx << 2]);
            acc[0][0] += a.x * b.x; acc[0][1] += a.x * b.y;
            acc[0][2] += a.x * b.z; acc[0][3] += a.x * b.w;
            acc[1][0] += a.y * b.x; acc[1][1] += a.y * b.y;
            acc[1][2] += a.y * b.z; acc[1][3] += a.y * b.w;
            acc[2][0] += a.z * b.x; acc[2][1] += a.z * b.y;
            acc[2][2] += a.z * b.z; acc[2][3] += a.z * b.w;
            acc[3][0] += a.w * b.x; acc[3][1] += a.w * b.y;
            acc[3][2] += a.w * b.z; acc[3][3] += a.w * b.w;
        }
        __syncthreads();
    }

    float bv[4] = {0.f, 0.f, 0.f, 0.f};
    #pragma unroll
    for (int j = 0; j < 4; j++) {
        int c = bn + (tx << 2) + j;
        bv[j] = (c < Ncols) ? bias[c] : 0.f;
    }
    #pragma unroll
    for (int i = 0; i < 4; i++) {
        int r = bm + (ty << 2) + i;
        if (r >= M) continue;
        #pragma unroll
        for (int j = 0; j < 4; j++) {
            int c = bn + (tx << 2) + j;
            if (c >= Ncols) continue;
            C[(size_t)r * Ncols + c] = acc[i][j] + bv[j];
        }
    }
}

// ---------------- edge scatter: one warp per edge, float4 atomics --------
__global__ void scatter_kernel(const int* __restrict__ src,
                               const int* __restrict__ dst,
                               const float* __restrict__ ew,
                               const float* __restrict__ xw,
                               float* __restrict__ agg) {
    int warp = (blockIdx.x * blockDim.x + threadIdx.x) >> 5;
    int lane = threadIdx.x & 31;
    if (warp >= EE) return;
    int s = src[warp];
    int d = dst[warp];
    float norm = g_dinv[s] * ew[warp] * g_dinv[d];
    float4 v = ((const float4*)(xw + (size_t)s * FH))[lane];
    v.x *= norm; v.y *= norm; v.z *= norm; v.w *= norm;
    atomicAdd((float4*)(agg + (size_t)d * FH + (lane << 2)), v);
}

// ---------------- bias + relu: xh = relu(agg + b) ----------------
__global__ void bias_relu_kernel(const float* __restrict__ agg,
                                 float* __restrict__ xh,
                                 const float* __restrict__ b) {
    size_t idx = (size_t)blockIdx.x * blockDim.x + threadIdx.x;
    if (idx >= (size_t)NN * FH) return;
    int f = (int)(idx & (FH - 1));
    xh[idx] = fmaxf(agg[idx] + b[f], 0.f);
}

// ---------------- GRU elementwise ----------------
__global__ void gru_kernel(const float* __restrict__ gi,
                           const float* __restrict__ gh,
                           const float* __restrict__ hprev,
                           float* __restrict__ hout) {
    size_t idx = (size_t)blockIdx.x * blockDim.x + threadIdx.x;
    if (idx >= (size_t)NN * FH) return;
    int n = (int)(idx >> 7);
    int j = (int)(idx & (FH - 1));
    size_t base = (size_t)n * H3 + j;
    float ir = gi[base          ];
    float iz = gi[base + FH     ];
    float in_ = gi[base + 2 * FH];
    float hr = gh[base          ];
    float hz = gh[base + FH     ];
    float hn = gh[base + 2 * FH];
    float hv = hprev[idx];
    float r = 1.f / (1.f + expf(-(ir + hr)));
    float z = 1.f / (1.f + expf(-(iz + hz)));
    float nn = tanhf(in_ + r * hn);
    hout[idx] = (1.f - z) * nn + z * hv;
}

// ---------------- host orchestration ----------------
extern "C" void kernel_launch(void* const* d_in, const int* in_sizes, int n_in,
                              void* d_out, int out_size) {
    const float* x     = (const float*)d_in[0];
    const int*   ei    = (const int*)  d_in[1];
    const float* ew    = (const float*)d_in[2];
    const float* h0    = (const float*)d_in[3];
    const float* linW  = (const float*)d_in[4];
    const float* linB  = (const float*)d_in[5];
    const float* convW = (const float*)d_in[6];
    const float* convB = (const float*)d_in[7];
    const float* Wih   = (const float*)d_in[8];
    const float* Whh   = (const float*)d_in[9];
    const float* bih   = (const float*)d_in[10];
    const float* bhh   = (const float*)d_in[11];
    const float* fcW   = (const float*)d_in[12];
    const float* fcB   = (const float*)d_in[13];
    float* out = (float*)d_out;

    const int* src = ei;
    const int* dst = ei + EE;

    // one-time: allow >48KB dynamic smem for tf32 instantiations
    static bool s_attr_done = false;
    if (!s_attr_done) {
        cudaFuncSetAttribute(gemm_tf32_kernel<false, true, true, false>,
                             cudaFuncAttributeMaxDynamicSharedMemorySize, GEMM_SMEM_BYTES);
        cudaFuncSetAttribute(gemm_tf32_kernel<true, true, false, false>,
                             cudaFuncAttributeMaxDynamicSharedMemorySize, GEMM_SMEM_BYTES);
        cudaFuncSetAttribute(gemm_tf32_kernel<false, false, false, true>,
                             cudaFuncAttributeMaxDynamicSharedMemorySize, GEMM_SMEM_BYTES);
        s_attr_done = true;
    }

    // scratch symbol addresses (not stream ops; graph-capture safe)
    float *p_xh, *p_xw, *p_h, *p_gi, *p_gh;
    cudaGetSymbolAddress((void**)&p_xh, g_xh);
    cudaGetSymbolAddress((void**)&p_xw, g_xw);
    cudaGetSymbolAddress((void**)&p_h,  g_h);
    cudaGetSymbolAddress((void**)&p_gi, g_gi);
    cudaGetSymbolAddress((void**)&p_gh, g_gh);
    float* p_agg = p_gi;   // reuse gi's first NN*FH floats as agg scratch

    const size_t NF = (size_t)NN * FH;
    const int EB = 256;

    const dim3 blk512(512);
    const dim3 grid128(1, (NN + 127) / 128);     // Ncols=128
    const dim3 grid384(3, (NN + 127) / 128);     // Ncols=384
    const size_t sm = GEMM_SMEM_BYTES;

    // degree + normalization
    init_deg_kernel<<<(NN + 255) / 256, 256>>>();
    accum_deg_kernel<<<(EE + EB - 1) / EB, EB>>>(dst, ew);
    dinv_kernel<<<(NN + 255) / 256, 256>>>();

    // xh = relu(x @ linW + linB)
    gemm_tf32_kernel<false, true, true, false><<<grid128, blk512, sm>>>(
        x, linW, linB, p_xh, nullptr, NN, FH);

    // h = GRU(xh, h0)
    gemm_tf32_kernel<true, true, false, false><<<grid384, blk512, sm>>>(
        p_xh, Wih, bih, p_gi, nullptr, NN, H3);
    gemm_tf32_kernel<true, true, false, false><<<grid384, blk512, sm>>>(
        h0, Whh, bhh, p_gh, nullptr, NN, H3);
    gru_kernel<<<(int)((NF + 255) / 256), 256>>>(p_gi, p_gh, h0, p_h);

    for (int l = 0; l < LL; l++) {
        const float* W = convW + (size_t)l * FH * FH;
        const float* b = convB + (size_t)l * FH;
        // xw = xh @ W ; agg = xw * dinv^2 (fused self-loop init)
        gemm_tf32_kernel<false, false, false, true><<<grid128, blk512, sm>>>(
            p_xh, W, nullptr, p_xw, p_agg, NN, FH);
        // edge scatter into agg (float4 vector atomics)
        scatter_kernel<<<(EE * 32 + 255) / 256, 256>>>(src, dst, ew, p_xw, p_agg);
        // xh = relu(agg + b)
        bias_relu_kernel<<<(int)((NF + 255) / 256), 256>>>(p_agg, p_xh, b);
        // h = GRU(xh, h)
        gemm_tf32_kernel<true, true, false, false><<<grid384, blk512, sm>>>(
            p_xh, Wih, bih, p_gi, nullptr, NN, H3);
        gemm_tf32_kernel<true, true, false, false><<<grid384, blk512, sm>>>(
            p_h, Whh, bhh, p_gh, nullptr, NN, H3);
        gru_kernel<<<(int)((NF + 255) / 256), 256>>>(p_gi, p_gh, p_h, p_h);
    }

    // out = h @ fcW + fcB (fp32 fallback: Ncols=40)
    {
        dim3 grid((CC + 63) / 64, (NN + 63) / 64);
        gemm_fc_kernel<<<grid, 256>>>(p_h, fcW, fcB, out, NN, CC);
    }
}

// round 10
// speedup vs baseline: 1.8835x; 1.0085x over previous
#include <cuda_runtime.h>
#include <cstdint>

// Problem constants (fixed by reference)
#define NN   100000
#define EE   1600000
#define FH   128      // F_IN == H == HG
#define H3   384      // 3*HG
#define CC   40
#define LL   3

// ---------------- scratch (device globals; no allocation allowed) ----------
__device__ float g_xh[(size_t)NN * FH];
__device__ float g_xw[(size_t)NN * FH];
__device__ float g_h [(size_t)NN * FH];
__device__ float g_gi[(size_t)NN * H3];   // first NN*FH also reused as agg
__device__ float g_gh[(size_t)NN * H3];
__device__ float g_deg [NN];
__device__ float g_dinv[NN];

// ---------------- degree / normalization ----------------
__global__ void init_deg_kernel() {
    int i = blockIdx.x * blockDim.x + threadIdx.x;
    if (i < NN) g_deg[i] = 1.0f;   // self-loop weight 1
}

__global__ void accum_deg_kernel(const int* __restrict__ dst,
                                 const float* __restrict__ ew) {
    int e = blockIdx.x * blockDim.x + threadIdx.x;
    if (e < EE) atomicAdd(&g_deg[dst[e]], ew[e]);
}

__global__ void dinv_kernel() {
    int i = blockIdx.x * blockDim.x + threadIdx.x;
    if (i < NN) g_dinv[i] = rsqrtf(g_deg[i]);   // deg >= 1 always
}

// =====================================================================
// TF32 tensor-core GEMM v5: C[M,Ncols] = A[M,128] * B (+bias)(+relu)
//   TRANSB=false: B is [128, Ncols] row-major
//   TRANSB=true : B is [Ncols, 128] row-major (C = A * B^T)
//   SELF=true  : additionally write agg[r] = C[r]*dinv[r]^2 (Ncols==128 only)
// CTA tile 128x128, K=128 resident in smem, row-major padded (TS=132).
// ldmatrix fragment loads, SOFTWARE-PIPELINED (double-buffered frags:
// prefetch k-step ks+1 before issuing ks's 8 MMAs, hiding LDS latency).
// 512 threads / 16 warps, warp tile 32x32, mma.m16n8k8.tf32.
// =====================================================================
#define TS 132
#define GEMM_SMEM_BYTES (2 * 128 * TS * 4)   // 135168 B

__device__ __forceinline__ float to_tf32(float v) {
    uint32_t o;
    asm volatile("cvt.rna.tf32.f32 %0, %1;" : "=r"(o) : "f"(v));
    return __uint_as_float(o);
}

__device__ __forceinline__ void ldsm4(uint32_t* r, uint32_t addr) {
    asm volatile(
        "ldmatrix.sync.aligned.m8n8.x4.shared.b16 {%0,%1,%2,%3}, [%4];"
        : "=r"(r[0]), "=r"(r[1]), "=r"(r[2]), "=r"(r[3]) : "r"(addr));
}

__device__ __forceinline__ void mma_tf32(float* d, const uint32_t* a,
                                         uint32_t b0, uint32_t b1) {
    asm volatile(
        "mma.sync.aligned.m16n8k8.row.col.f32.tf32.tf32.f32 "
        "{%0,%1,%2,%3}, {%4,%5,%6,%7}, {%8,%9}, {%0,%1,%2,%3};\n"
        : "+f"(d[0]), "+f"(d[1]), "+f"(d[2]), "+f"(d[3])
        : "r"(a[0]), "r"(a[1]), "r"(a[2]), "r"(a[3]), "r"(b0), "r"(b1));
}

template<bool TRANSB, bool BIAS, bool RELU, bool SELF>
__global__ __launch_bounds__(512, 1)
void gemm_tf32_kernel(const float* __restrict__ A,
                      const float* __restrict__ B,
                      const float* __restrict__ bias,
                      float* __restrict__ C,
                      float* __restrict__ agg,
                      int M, int Ncols) {
    extern __shared__ float smem[];
    float* As = smem;             // [128][TS]
    float* Bs = smem + 128 * TS;  // [128][TS]

    const int tid  = threadIdx.x;
    const int lane = tid & 31;
    const int wid  = tid >> 5;                 // 0..15
    const int lr   = lane >> 2;                // 0..7
    const int lc   = lane & 3;                 // 0..3
    const int bm = blockIdx.y * 128;
    const int bn = blockIdx.x * 128;

    // ---- fill As[m][k] (coalesced float4, conflict-free STS.128) ----
    #pragma unroll
    for (int it = 0; it < 8; it++) {
        int i = it * 512 + tid;
        int m = i >> 5;
        int q = (i & 31) << 2;
        int gr = bm + m;
        float4 v = make_float4(0.f, 0.f, 0.f, 0.f);
        if (gr < M) v = *(const float4*)(A + (size_t)gr * 128 + q);
        float4 w = make_float4(to_tf32(v.x), to_tf32(v.y),
                               to_tf32(v.z), to_tf32(v.w));
        *(float4*)(As + m * TS + q) = w;
    }
    // ---- fill Bs[n][k] ----
    if (TRANSB) {
        #pragma unroll
        for (int it = 0; it < 8; it++) {
            int i = it * 512 + tid;
            int n = i >> 5;
            int q = (i & 31) << 2;
            float4 v = *(const float4*)(B + (size_t)(bn + n) * 128 + q);
            float4 w = make_float4(to_tf32(v.x), to_tf32(v.y),
                                   to_tf32(v.z), to_tf32(v.w));
            *(float4*)(Bs + n * TS + q) = w;
        }
    } else {
        #pragma unroll
        for (int it = 0; it < 8; it++) {
            int i = it * 512 + tid;
            int k = i >> 5;
            int p = (i & 31) << 2;
            float4 v = *(const float4*)(B + (size_t)k * Ncols + bn + p);
            Bs[(p + 0) * TS + k] = to_tf32(v.x);
            Bs[(p + 1) * TS + k] = to_tf32(v.y);
            Bs[(p + 2) * TS + k] = to_tf32(v.z);
            Bs[(p + 3) * TS + k] = to_tf32(v.w);
        }
    }
    __syncthreads();

    // warp tile: 32 rows x 32 cols; warp grid 4x4
    const int wtm = wid & 3;
    const int wtn = wid >> 2;

    uint32_t as_base = (uint32_t)__cvta_generic_to_shared(As);
    uint32_t bs_base = (uint32_t)__cvta_generic_to_shared(Bs);
    int arow = (lane & 7) + ((lane >> 3) & 1) * 8;
    int acol = (lane >> 4) << 2;
    uint32_t aAddr0 = as_base + (((wtm * 32 +  0 + arow) * TS + acol) << 2);
    uint32_t aAddr1 = as_base + (((wtm * 32 + 16 + arow) * TS + acol) << 2);
    int brow = (lane & 7) + ((lane >> 4) << 3);
    int bcol = ((lane >> 3) & 1) << 2;
    uint32_t bAddr0 = bs_base + (((wtn * 32 +  0 + brow) * TS + bcol) << 2);
    uint32_t bAddr1 = bs_base + (((wtn * 32 + 16 + brow) * TS + bcol) << 2);

    float acc[2][4][4];
    #pragma unroll
    for (int mi = 0; mi < 2; mi++)
        #pragma unroll
        for (int ni = 0; ni < 4; ni++)
            #pragma unroll
            for (int j = 0; j < 4; j++) acc[mi][ni][j] = 0.f;

    // ---- software-pipelined mainloop: prefetch ks+1, compute ks ----
    uint32_t a0[2][4], a1[2][4], b01[2][4], b23[2][4];
    ldsm4(a0[0],  aAddr0);
    ldsm4(a1[0],  aAddr1);
    ldsm4(b01[0], bAddr0);
    ldsm4(b23[0], bAddr1);

    #pragma unroll
    for (int ks = 0; ks < 16; ks++) {
        const int cur = ks & 1;
        const int nxt = cur ^ 1;
        if (ks < 15) {
            uint32_t koff = (uint32_t)(ks + 1) * 32;   // 8 floats/step
            ldsm4(a0[nxt],  aAddr0 + koff);
            ldsm4(a1[nxt],  aAddr1 + koff);
            ldsm4(b01[nxt], bAddr0 + koff);
            ldsm4(b23[nxt], bAddr1 + koff);
        }
        mma_tf32(acc[0][0], a0[cur], b01[cur][0], b01[cur][1]);
        mma_tf32(acc[0][1], a0[cur], b01[cur][2], b01[cur][3]);
        mma_tf32(acc[0][2], a0[cur], b23[cur][0], b23[cur][1]);
        mma_tf32(acc[0][3], a0[cur], b23[cur][2], b23[cur][3]);
        mma_tf32(acc[1][0], a1[cur], b01[cur][0], b01[cur][1]);
        mma_tf32(acc[1][1], a1[cur], b01[cur][2], b01[cur][3]);
        mma_tf32(acc[1][2], a1[cur], b23[cur][0], b23[cur][1]);
        mma_tf32(acc[1][3], a1[cur], b23[cur][2], b23[cur][3]);
    }

    // ---- epilogue ----
    #pragma unroll
    for (int mi = 0; mi < 2; mi++) {
        int r0 = bm + wtm * 32 + mi * 16 + lr;
        int r1 = r0 + 8;
        float di0 = 0.f, di1 = 0.f;
        if (SELF) {
            if (r0 < M) di0 = g_dinv[r0];
            if (r1 < M) di1 = g_dinv[r1];
        }
        #pragma unroll
        for (int ni = 0; ni < 4; ni++) {
            int c0 = bn + wtn * 32 + ni * 8 + (lc << 1);
            float b0 = 0.f, b1 = 0.f;
            if (BIAS) { b0 = bias[c0]; b1 = bias[c0 + 1]; }
            float v0 = acc[mi][ni][0] + b0;
            float v1 = acc[mi][ni][1] + b1;
            float v2 = acc[mi][ni][2] + b0;
            float v3 = acc[mi][ni][3] + b1;
            if (RELU) {
                v0 = fmaxf(v0, 0.f); v1 = fmaxf(v1, 0.f);
                v2 = fmaxf(v2, 0.f); v3 = fmaxf(v3, 0.f);
            }
            if (r0 < M) {
                *(float2*)(C + (size_t)r0 * Ncols + c0) = make_float2(v0, v1);
                if (SELF)
                    *(float2*)(agg + (size_t)r0 * 128 + c0) =
                        make_float2(v0 * di0 * di0, v1 * di0 * di0);
            }
            if (r1 < M) {
                *(float2*)(C + (size_t)r1 * Ncols + c0) = make_float2(v2, v3);
                if (SELF)
                    *(float2*)(agg + (size_t)r1 * 128 + c0) =
                        make_float2(v2 * di1 * di1, v3 * di1 * di1);
            }
        }
    }
}

// ---------------- fp32 fallback GEMM (used for fc, Ncols=40) --------------
__global__ void gemm_fc_kernel(const float* __restrict__ A,
                               const float* __restrict__ B,
                               const float* __restrict__ bias,
                               float* __restrict__ C,
                               int M, int Ncols) {
    constexpr int K  = 128;
    constexpr int BM = 64, BN = 64, BK = 16;
    __shared__ float As[BK][BM + 4];
    __shared__ float Bs[BK][BN + 4];

    const int tid = threadIdx.x;
    const int bm = blockIdx.y * BM;
    const int bn = blockIdx.x * BN;
    const int tx = tid & 15;
    const int ty = tid >> 4;

    float acc[4][4] = {};

    for (int k0 = 0; k0 < K; k0 += BK) {
        {
            const int arow = tid >> 2;
            const int acol = (tid & 3) << 2;
            float4 av = make_float4(0.f, 0.f, 0.f, 0.f);
            const int gr = bm + arow;
            if (gr < M)
                av = *(const float4*)(A + (size_t)gr * K + k0 + acol);
            As[acol + 0][arow] = av.x;
            As[acol + 1][arow] = av.y;
            As[acol + 2][arow] = av.z;
            As[acol + 3][arow] = av.w;
        }
        {
            const int brow = tid >> 4;
            const int bcol = (tid & 15) << 2;
            const int gc = bn + bcol;
            Bs[brow][bcol + 0] = (gc + 0 < Ncols) ? B[(size_t)(k0 + brow) * Ncols + gc + 0] : 0.f;
            Bs[brow][bcol + 1] = (gc + 1 < Ncols) ? B[(size_t)(k0 + brow) * Ncols + gc + 1] : 0.f;
            Bs[brow][bcol + 2] = (gc + 2 < Ncols) ? B[(size_t)(k0 + brow) * Ncols + gc + 2] : 0.f;
            Bs[brow][bcol + 3] = (gc + 3 < Ncols) ? B[(size_t)(k0 + brow) * Ncols + gc + 3] : 0.f;
        }
        __syncthreads();

        #pragma unroll
        for (int k = 0; k < BK; k++) {
            float4 a = *(const float4*)(&As[k][ty << 2]);
            float4 b = *(const float4*)(&Bs[k][tx << 2]);
            acc[0][0] += a.x * b.x; acc[0][1] += a.x * b.y;
            acc[0][2] += a.x * b.z; acc[0][3] += a.x * b.w;
            acc[1][0] += a.y * b.x; acc[1][1] += a.y * b.y;
            acc[1][2] += a.y * b.z; acc[1][3] += a.y * b.w;
            acc[2][0] += a.z * b.x; acc[2][1] += a.z * b.y;
            acc[2][2] += a.z * b.z; acc[2][3] += a.z * b.w;
            acc[3][0] += a.w * b.x; acc[3][1] += a.w * b.y;
            acc[3][2] += a.w * b.z; acc[3][3] += a.w * b.w;
        }
        __syncthreads();
    }

    float bv[4] = {0.f, 0.f, 0.f, 0.f};
    #pragma unroll
    for (int j = 0; j < 4; j++) {
        int c = bn + (tx << 2) + j;
        bv[j] = (c < Ncols) ? bias[c] : 0.f;
    }
    #pragma unroll
    for (int i = 0; i < 4; i++) {
        int r = bm + (ty << 2) + i;
        if (r >= M) continue;
        #pragma unroll
        for (int j = 0; j < 4; j++) {
            int c = bn + (tx << 2) + j;
            if (c >= Ncols) continue;
            C[(size_t)r * Ncols + c] = acc[i][j] + bv[j];
        }
    }
}

// ---------------- edge scatter: one warp per edge, float4 atomics --------
__global__ void scatter_kernel(const int* __restrict__ src,
                               const int* __restrict__ dst,
                               const float* __restrict__ ew,
                               const float* __restrict__ xw,
                               float* __restrict__ agg) {
    int warp = (blockIdx.x * blockDim.x + threadIdx.x) >> 5;
    int lane = threadIdx.x & 31;
    if (warp >= EE) return;
    int s = src[warp];
    int d = dst[warp];
    float norm = g_dinv[s] * ew[warp] * g_dinv[d];
    float4 v = ((const float4*)(xw + (size_t)s * FH))[lane];
    v.x *= norm; v.y *= norm; v.z *= norm; v.w *= norm;
    atomicAdd((float4*)(agg + (size_t)d * FH + (lane << 2)), v);
}

// ---------------- bias + relu: xh = relu(agg + b) ----------------
__global__ void bias_relu_kernel(const float* __restrict__ agg,
                                 float* __restrict__ xh,
                                 const float* __restrict__ b) {
    size_t idx = (size_t)blockIdx.x * blockDim.x + threadIdx.x;
    if (idx >= (size_t)NN * FH) return;
    int f = (int)(idx & (FH - 1));
    xh[idx] = fmaxf(agg[idx] + b[f], 0.f);
}

// ---------------- GRU elementwise ----------------
__global__ void gru_kernel(const float* __restrict__ gi,
                           const float* __restrict__ gh,
                           const float* __restrict__ hprev,
                           float* __restrict__ hout) {
    size_t idx = (size_t)blockIdx.x * blockDim.x + threadIdx.x;
    if (idx >= (size_t)NN * FH) return;
    int n = (int)(idx >> 7);
    int j = (int)(idx & (FH - 1));
    size_t base = (size_t)n * H3 + j;
    float ir = gi[base          ];
    float iz = gi[base + FH     ];
    float in_ = gi[base + 2 * FH];
    float hr = gh[base          ];
    float hz = gh[base + FH     ];
    float hn = gh[base + 2 * FH];
    float hv = hprev[idx];
    float r = 1.f / (1.f + expf(-(ir + hr)));
    float z = 1.f / (1.f + expf(-(iz + hz)));
    float nn = tanhf(in_ + r * hn);
    hout[idx] = (1.f - z) * nn + z * hv;
}

// ---------------- host orchestration ----------------
extern "C" void kernel_launch(void* const* d_in, const int* in_sizes, int n_in,
                              void* d_out, int out_size) {
    const float* x     = (const float*)d_in[0];
    const int*   ei    = (const int*)  d_in[1];
    const float* ew    = (const float*)d_in[2];
    const float* h0    = (const float*)d_in[3];
    const float* linW  = (const float*)d_in[4];
    const float* linB  = (const float*)d_in[5];
    const float* convW = (const float*)d_in[6];
    const float* convB = (const float*)d_in[7];
    const float* Wih   = (const float*)d_in[8];
    const float* Whh   = (const float*)d_in[9];
    const float* bih   = (const float*)d_in[10];
    const float* bhh   = (const float*)d_in[11];
    const float* fcW   = (const float*)d_in[12];
    const float* fcB   = (const float*)d_in[13];
    float* out = (float*)d_out;

    const int* src = ei;
    const int* dst = ei + EE;

    // one-time: allow >48KB dynamic smem for tf32 instantiations
    static bool s_attr_done = false;
    if (!s_attr_done) {
        cudaFuncSetAttribute(gemm_tf32_kernel<false, true, true, false>,
                             cudaFuncAttributeMaxDynamicSharedMemorySize, GEMM_SMEM_BYTES);
        cudaFuncSetAttribute(gemm_tf32_kernel<true, true, false, false>,
                             cudaFuncAttributeMaxDynamicSharedMemorySize, GEMM_SMEM_BYTES);
        cudaFuncSetAttribute(gemm_tf32_kernel<false, false, false, true>,
                             cudaFuncAttributeMaxDynamicSharedMemorySize, GEMM_SMEM_BYTES);
        s_attr_done = true;
    }

    // scratch symbol addresses (not stream ops; graph-capture safe)
    float *p_xh, *p_xw, *p_h, *p_gi, *p_gh;
    cudaGetSymbolAddress((void**)&p_xh, g_xh);
    cudaGetSymbolAddress((void**)&p_xw, g_xw);
    cudaGetSymbolAddress((void**)&p_h,  g_h);
    cudaGetSymbolAddress((void**)&p_gi, g_gi);
    cudaGetSymbolAddress((void**)&p_gh, g_gh);
    float* p_agg = p_gi;   // reuse gi's first NN*FH floats as agg scratch

    const size_t NF = (size_t)NN * FH;
    const int EB = 256;

    const dim3 blk512(512);
    const dim3 grid128(1, (NN + 127) / 128);     // Ncols=128
    const dim3 grid384(3, (NN + 127) / 128);     // Ncols=384
    const size_t sm = GEMM_SMEM_BYTES;

    // degree + normalization
    init_deg_kernel<<<(NN + 255) / 256, 256>>>();
    accum_deg_kernel<<<(EE + EB - 1) / EB, EB>>>(dst, ew);
    dinv_kernel<<<(NN + 255) / 256, 256>>>();

    // xh = relu(x @ linW + linB)
    gemm_tf32_kernel<false, true, true, false><<<grid128, blk512, sm>>>(
        x, linW, linB, p_xh, nullptr, NN, FH);

    // h = GRU(xh, h0)
    gemm_tf32_kernel<true, true, false, false><<<grid384, blk512, sm>>>(
        p_xh, Wih, bih, p_gi, nullptr, NN, H3);
    gemm_tf32_kernel<true, true, false, false><<<grid384, blk512, sm>>>(
        h0, Whh, bhh, p_gh, nullptr, NN, H3);
    gru_kernel<<<(int)((NF + 255) / 256), 256>>>(p_gi, p_gh, h0, p_h);

    for (int l = 0; l < LL; l++) {
        const float* W = convW + (size_t)l * FH * FH;
        const float* b = convB + (size_t)l * FH;
        // xw = xh @ W ; agg = xw * dinv^2 (fused self-loop init)
        gemm_tf32_kernel<false, false, false, true><<<grid128, blk512, sm>>>(
            p_xh, W, nullptr, p_xw, p_agg, NN, FH);
        // edge scatter into agg (float4 vector atomics)
        scatter_kernel<<<(EE * 32 + 255) / 256, 256>>>(src, dst, ew, p_xw, p_agg);
        // xh = relu(agg + b)
        bias_relu_kernel<<<(int)((NF + 255) / 256), 256>>>(p_agg, p_xh, b);
        // h = GRU(xh, h)
        gemm_tf32_kernel<true, true, false, false><<<grid384, blk512, sm>>>(
            p_xh, Wih, bih, p_gi, nullptr, NN, H3);
        gemm_tf32_kernel<true, true, false, false><<<grid384, blk512, sm>>>(
            p_h, Whh, bhh, p_gh, nullptr, NN, H3);
        gru_kernel<<<(int)((NF + 255) / 256), 256>>>(p_gi, p_gh, p_h, p_h);
    }

    // out = h @ fcW + fcB (fp32 fallback: Ncols=40)
    {
        dim3 grid((CC + 63) / 64, (NN + 63) / 64);
        gemm_fc_kernel<<<grid, 256>>>(p_h, fcW, fcB, out, NN, CC);
    }
}

// round 12
// speedup vs baseline: 2.1664x; 1.1502x over previous
#include <cuda_runtime.h>
#include <cstdint>

// Problem constants (fixed by reference)
#define NN   100000
#define EE   1600000
#define FH   128      // F_IN == H == HG
#define H3   384      // 3*HG
#define CC   40
#define LL   3

// ---------------- scratch (device globals; no allocation allowed) ----------
__device__ float g_xh[(size_t)NN * FH];
__device__ float g_xw[(size_t)NN * FH];
__device__ float g_h [(size_t)NN * FH];
__device__ float g_agg[(size_t)NN * FH];
__device__ float g_deg [NN];
__device__ float g_dinv[NN];

// ---------------- degree / normalization ----------------
__global__ void init_deg_kernel() {
    int i = blockIdx.x * blockDim.x + threadIdx.x;
    if (i < NN) g_deg[i] = 1.0f;   // self-loop weight 1
}

__global__ void accum_deg_kernel(const int* __restrict__ dst,
                                 const float* __restrict__ ew) {
    int e = blockIdx.x * blockDim.x + threadIdx.x;
    if (e < EE) atomicAdd(&g_deg[dst[e]], ew[e]);
}

__global__ void dinv_kernel() {
    int i = blockIdx.x * blockDim.x + threadIdx.x;
    if (i < NN) g_dinv[i] = rsqrtf(g_deg[i]);   // deg >= 1 always
}

// ---------------- shared MMA machinery (measured-good from R8) ------------
#define TS 132

__device__ __forceinline__ float to_tf32(float v) {
    uint32_t o;
    asm volatile("cvt.rna.tf32.f32 %0, %1;" : "=r"(o) : "f"(v));
    return __uint_as_float(o);
}

__device__ __forceinline__ void ldsm4(uint32_t* r, uint32_t addr) {
    asm volatile(
        "ldmatrix.sync.aligned.m8n8.x4.shared.b16 {%0,%1,%2,%3}, [%4];"
        : "=r"(r[0]), "=r"(r[1]), "=r"(r[2]), "=r"(r[3]) : "r"(addr));
}

__device__ __forceinline__ void mma_tf32(float* d, const uint32_t* a,
                                         uint32_t b0, uint32_t b1) {
    asm volatile(
        "mma.sync.aligned.m16n8k8.row.col.f32.tf32.tf32.f32 "
        "{%0,%1,%2,%3}, {%4,%5,%6,%7}, {%8,%9}, {%0,%1,%2,%3};\n"
        : "+f"(d[0]), "+f"(d[1]), "+f"(d[2]), "+f"(d[3])
        : "r"(a[0]), "r"(a[1]), "r"(a[2]), "r"(a[3]), "r"(b0), "r"(b1));
}

// one full K=128 pass: acc[2][4][4] = Atile(32 rows) x Btile(32 cols)^T
__device__ __forceinline__ void mma_pass(uint32_t aA0, uint32_t aA1,
                                         uint32_t bA0, uint32_t bA1,
                                         float acc[2][4][4]) {
    #pragma unroll
    for (int mi = 0; mi < 2; mi++)
        #pragma unroll
        for (int ni = 0; ni < 4; ni++)
            #pragma unroll
            for (int j = 0; j < 4; j++) acc[mi][ni][j] = 0.f;
    #pragma unroll
    for (int ks = 0; ks < 16; ks++) {
        uint32_t a0[4], a1[4], b01[4], b23[4];
        uint32_t ko = (uint32_t)ks * 32;
        ldsm4(a0,  aA0 + ko);
        ldsm4(a1,  aA1 + ko);
        ldsm4(b01, bA0 + ko);
        ldsm4(b23, bA1 + ko);
        mma_tf32(acc[0][0], a0, b01[0], b01[1]);
        mma_tf32(acc[0][1], a0, b01[2], b01[3]);
        mma_tf32(acc[0][2], a0, b23[0], b23[1]);
        mma_tf32(acc[0][3], a0, b23[2], b23[3]);
        mma_tf32(acc[1][0], a1, b01[0], b01[1]);
        mma_tf32(acc[1][1], a1, b01[2], b01[3]);
        mma_tf32(acc[1][2], a1, b23[0], b23[1]);
        mma_tf32(acc[1][3], a1, b23[2], b23[3]);
    }
}

__device__ __forceinline__ float sigm(float x) {
    return 1.f / (1.f + expf(-x));
}

// =====================================================================
// TF32 GEMM (lin / conv): C[M,Ncols] = A[M,128] * B[128,Ncols] (+bias)(+relu)
//   SELF=true: additionally write agg[r] = C[r]*dinv[r]^2 (Ncols==128)
// =====================================================================
#define GEMM_SMEM_BYTES (2 * 128 * TS * 4)   // 135168 B

template<bool BIAS, bool RELU, bool SELF>
__global__ __launch_bounds__(512, 1)
void gemm_tf32_kernel(const float* __restrict__ A,
                      const float* __restrict__ B,
                      const float* __restrict__ bias,
                      float* __restrict__ C,
                      float* __restrict__ agg,
                      int M, int Ncols) {
    extern __shared__ float smem[];
    float* As = smem;             // [128][TS]
    float* Bs = smem + 128 * TS;  // [128][TS]

    const int tid  = threadIdx.x;
    const int lane = tid & 31;
    const int wid  = tid >> 5;
    const int lr   = lane >> 2;
    const int lc   = lane & 3;
    const int bm = blockIdx.y * 128;
    const int bn = blockIdx.x * 128;

    #pragma unroll
    for (int it = 0; it < 8; it++) {
        int i = it * 512 + tid;
        int m = i >> 5;
        int q = (i & 31) << 2;
        int gr = bm + m;
        float4 v = make_float4(0.f, 0.f, 0.f, 0.f);
        if (gr < M) v = *(const float4*)(A + (size_t)gr * 128 + q);
        *(float4*)(As + m * TS + q) = make_float4(to_tf32(v.x), to_tf32(v.y),
                                                  to_tf32(v.z), to_tf32(v.w));
    }
    // transpose fill: Bs[n][k] = B[k][bn+n]
    #pragma unroll
    for (int it = 0; it < 8; it++) {
        int i = it * 512 + tid;
        int k = i >> 5;
        int p = (i & 31) << 2;
        float4 v = *(const float4*)(B + (size_t)k * Ncols + bn + p);
        Bs[(p + 0) * TS + k] = to_tf32(v.x);
        Bs[(p + 1) * TS + k] = to_tf32(v.y);
        Bs[(p + 2) * TS + k] = to_tf32(v.z);
        Bs[(p + 3) * TS + k] = to_tf32(v.w);
    }
    __syncthreads();

    const int wtm = wid & 3;
    const int wtn = wid >> 2;
    uint32_t as_base = (uint32_t)__cvta_generic_to_shared(As);
    uint32_t bs_base = (uint32_t)__cvta_generic_to_shared(Bs);
    int arow = (lane & 7) + ((lane >> 3) & 1) * 8;
    int acol = (lane >> 4) << 2;
    int brow = (lane & 7) + ((lane >> 4) << 3);
    int bcol = ((lane >> 3) & 1) << 2;
    uint32_t aA0 = as_base + (((wtm * 32 +  0 + arow) * TS + acol) << 2);
    uint32_t aA1 = as_base + (((wtm * 32 + 16 + arow) * TS + acol) << 2);
    uint32_t bA0 = bs_base + (((wtn * 32 +  0 + brow) * TS + bcol) << 2);
    uint32_t bA1 = bs_base + (((wtn * 32 + 16 + brow) * TS + bcol) << 2);

    float acc[2][4][4];
    mma_pass(aA0, aA1, bA0, bA1, acc);

    #pragma unroll
    for (int mi = 0; mi < 2; mi++) {
        int r0 = bm + wtm * 32 + mi * 16 + lr;
        int r1 = r0 + 8;
        float di0 = 0.f, di1 = 0.f;
        if (SELF) {
            if (r0 < M) di0 = g_dinv[r0];
            if (r1 < M) di1 = g_dinv[r1];
        }
        #pragma unroll
        for (int ni = 0; ni < 4; ni++) {
            int c0 = bn + wtn * 32 + ni * 8 + (lc << 1);
            float b0 = 0.f, b1 = 0.f;
            if (BIAS) { b0 = bias[c0]; b1 = bias[c0 + 1]; }
            float v0 = acc[mi][ni][0] + b0;
            float v1 = acc[mi][ni][1] + b1;
            float v2 = acc[mi][ni][2] + b0;
            float v3 = acc[mi][ni][3] + b1;
            if (RELU) {
                v0 = fmaxf(v0, 0.f); v1 = fmaxf(v1, 0.f);
                v2 = fmaxf(v2, 0.f); v3 = fmaxf(v3, 0.f);
            }
            if (r0 < M) {
                *(float2*)(C + (size_t)r0 * Ncols + c0) = make_float2(v0, v1);
                if (SELF)
                    *(float2*)(agg + (size_t)r0 * 128 + c0) =
                        make_float2(v0 * di0 * di0, v1 * di0 * di0);
            }
            if (r1 < M) {
                *(float2*)(C + (size_t)r1 * Ncols + c0) = make_float2(v2, v3);
                if (SELF)
                    *(float2*)(agg + (size_t)r1 * 128 + c0) =
                        make_float2(v2 * di1 * di1, v3 * di1 * di1);
            }
        }
    }
}

// =====================================================================
// FUSED GRU: h' = GRU(xh, h) in ONE kernel. CTA = 128 nodes x 128 gates.
// smem: Axh (tf32), Ah (RAW fp32: tf32-truncated by MMA, exact in blend),
// Ws (one 128x128 weight slice at a time, 6 slices looped), biases.
// Gate order r -> n -> z keeps <=96 acc registers live.
// Traffic/GRU: 102MB read + 51MB write (vs 820MB unfused).
// =====================================================================
#define GRU_SMEM_BYTES (3 * 128 * TS * 4 + 2 * H3 * 4)   // 205824 B

__device__ __forceinline__ void load_w(float* Ws, const float* __restrict__ W,
                                       int tid) {
    #pragma unroll
    for (int it = 0; it < 8; it++) {
        int i = it * 512 + tid;
        int n = i >> 5;
        int q = (i & 31) << 2;
        float4 v = *(const float4*)(W + (size_t)n * 128 + q);
        *(float4*)(Ws + n * TS + q) = make_float4(to_tf32(v.x), to_tf32(v.y),
                                                  to_tf32(v.z), to_tf32(v.w));
    }
}

__global__ __launch_bounds__(512, 1)
void gru_fused_kernel(const float* __restrict__ xh,
                      const float* __restrict__ hin,
                      const float* __restrict__ Wih,
                      const float* __restrict__ Whh,
                      const float* __restrict__ bih,
                      const float* __restrict__ bhh,
                      float* __restrict__ hout,
                      int M) {
    extern __shared__ float smem[];
    float* Axh = smem;                 // [128][TS] tf32
    float* Ah  = smem + 128 * TS;      // [128][TS] raw fp32
    float* Ws  = smem + 256 * TS;      // [128][TS] weight slice
    float* bi_s = smem + 384 * TS;     // [384]
    float* bh_s = bi_s + H3;           // [384]

    const int tid  = threadIdx.x;
    const int lane = tid & 31;
    const int wid  = tid >> 5;
    const int lr   = lane >> 2;
    const int lc   = lane & 3;
    const int bm = blockIdx.x * 128;

    // ---- fill Axh (tf32) and Ah (raw) ----
    #pragma unroll
    for (int it = 0; it < 8; it++) {
        int i = it * 512 + tid;
        int m = i >> 5;
        int q = (i & 31) << 2;
        int gr = bm + m;
        float4 vx = make_float4(0.f, 0.f, 0.f, 0.f);
        float4 vh = make_float4(0.f, 0.f, 0.f, 0.f);
        if (gr < M) {
            vx = *(const float4*)(xh  + (size_t)gr * 128 + q);
            vh = *(const float4*)(hin + (size_t)gr * 128 + q);
        }
        *(float4*)(Axh + m * TS + q) = make_float4(to_tf32(vx.x), to_tf32(vx.y),
                                                   to_tf32(vx.z), to_tf32(vx.w));
        *(float4*)(Ah + m * TS + q) = vh;
    }
    if (tid < H3) { bi_s[tid] = bih[tid]; bh_s[tid] = bhh[tid]; }

    const int wtm = wid & 3;
    const int wtn = wid >> 2;
    int arow = (lane & 7) + ((lane >> 3) & 1) * 8;
    int acol = (lane >> 4) << 2;
    int brow = (lane & 7) + ((lane >> 4) << 3);
    int bcol = ((lane >> 3) & 1) << 2;
    uint32_t axh_b = (uint32_t)__cvta_generic_to_shared(Axh);
    uint32_t ah_b  = (uint32_t)__cvta_generic_to_shared(Ah);
    uint32_t ws_b  = (uint32_t)__cvta_generic_to_shared(Ws);
    uint32_t aO0 = ((wtm * 32 +  0 + arow) * TS + acol) << 2;
    uint32_t aO1 = ((wtm * 32 + 16 + arow) * TS + acol) << 2;
    uint32_t bO0 = ((wtn * 32 +  0 + brow) * TS + bcol) << 2;
    uint32_t bO1 = ((wtn * 32 + 16 + brow) * TS + bcol) << 2;

    float gi[2][4][4], gh[2][4][4], ra[2][4][4], na[2][4][4];

    // ======== gate r (slice 0) ========
    load_w(Ws, Wih, tid);
    __syncthreads();                       // covers Axh/Ah/bias fills too
    mma_pass(axh_b + aO0, axh_b + aO1, ws_b + bO0, ws_b + bO1, gi);
    __syncthreads();
    load_w(Ws, Whh, tid);
    __syncthreads();
    mma_pass(ah_b + aO0, ah_b + aO1, ws_b + bO0, ws_b + bO1, gh);
    #pragma unroll
    for (int mi = 0; mi < 2; mi++)
        #pragma unroll
        for (int ni = 0; ni < 4; ni++) {
            int col = wtn * 32 + ni * 8 + (lc << 1);
            float bs0 = bi_s[col] + bh_s[col];
            float bs1 = bi_s[col + 1] + bh_s[col + 1];
            ra[mi][ni][0] = sigm(gi[mi][ni][0] + gh[mi][ni][0] + bs0);
            ra[mi][ni][1] = sigm(gi[mi][ni][1] + gh[mi][ni][1] + bs1);
            ra[mi][ni][2] = sigm(gi[mi][ni][2] + gh[mi][ni][2] + bs0);
            ra[mi][ni][3] = sigm(gi[mi][ni][3] + gh[mi][ni][3] + bs1);
        }

    // ======== gate n (slice 2) ========
    __syncthreads();
    load_w(Ws, Wih + 2 * 128 * 128, tid);
    __syncthreads();
    mma_pass(axh_b + aO0, axh_b + aO1, ws_b + bO0, ws_b + bO1, gi);
    __syncthreads();
    load_w(Ws, Whh + 2 * 128 * 128, tid);
    __syncthreads();
    mma_pass(ah_b + aO0, ah_b + aO1, ws_b + bO0, ws_b + bO1, gh);
    #pragma unroll
    for (int mi = 0; mi < 2; mi++)
        #pragma unroll
        for (int ni = 0; ni < 4; ni++) {
            int col = wtn * 32 + ni * 8 + (lc << 1);
            float bi0 = bi_s[256 + col], bi1 = bi_s[256 + col + 1];
            float bh0 = bh_s[256 + col], bh1 = bh_s[256 + col + 1];
            na[mi][ni][0] = tanhf(gi[mi][ni][0] + bi0 + ra[mi][ni][0] * (gh[mi][ni][0] + bh0));
            na[mi][ni][1] = tanhf(gi[mi][ni][1] + bi1 + ra[mi][ni][1] * (gh[mi][ni][1] + bh1));
            na[mi][ni][2] = tanhf(gi[mi][ni][2] + bi0 + ra[mi][ni][2] * (gh[mi][ni][2] + bh0));
            na[mi][ni][3] = tanhf(gi[mi][ni][3] + bi1 + ra[mi][ni][3] * (gh[mi][ni][3] + bh1));
        }

    // ======== gate z (slice 1) + blend + store ========
    __syncthreads();
    load_w(Ws, Wih + 128 * 128, tid);
    __syncthreads();
    mma_pass(axh_b + aO0, axh_b + aO1, ws_b + bO0, ws_b + bO1, gi);
    __syncthreads();
    load_w(Ws, Whh + 128 * 128, tid);
    __syncthreads();
    mma_pass(ah_b + aO0, ah_b + aO1, ws_b + bO0, ws_b + bO1, gh);
    #pragma unroll
    for (int mi = 0; mi < 2; mi++) {
        int row0 = wtm * 32 + mi * 16 + lr;
        int row1 = row0 + 8;
        int gr0 = bm + row0, gr1 = bm + row1;
        #pragma unroll
        for (int ni = 0; ni < 4; ni++) {
            int col = wtn * 32 + ni * 8 + (lc << 1);
            float bs0 = bi_s[128 + col] + bh_s[128 + col];
            float bs1 = bi_s[128 + col + 1] + bh_s[128 + col + 1];
            float z0 = sigm(gi[mi][ni][0] + gh[mi][ni][0] + bs0);
            float z1 = sigm(gi[mi][ni][1] + gh[mi][ni][1] + bs1);
            float z2 = sigm(gi[mi][ni][2] + gh[mi][ni][2] + bs0);
            float z3 = sigm(gi[mi][ni][3] + gh[mi][ni][3] + bs1);
            float2 h0v = *(float2*)(Ah + row0 * TS + col);
            float2 h1v = *(float2*)(Ah + row1 * TS + col);
            float v0 = (1.f - z0) * na[mi][ni][0] + z0 * h0v.x;
            float v1 = (1.f - z1) * na[mi][ni][1] + z1 * h0v.y;
            float v2 = (1.f - z2) * na[mi][ni][2] + z2 * h1v.x;
            float v3 = (1.f - z3) * na[mi][ni][3] + z3 * h1v.y;
            if (gr0 < M) *(float2*)(hout + (size_t)gr0 * 128 + col) = make_float2(v0, v1);
            if (gr1 < M) *(float2*)(hout + (size_t)gr1 * 128 + col) = make_float2(v2, v3);
        }
    }
}

// ---------------- fp32 fallback GEMM (fc, Ncols=40) ----------------------
__global__ void gemm_fc_kernel(const float* __restrict__ A,
                               const float* __restrict__ B,
                               const float* __restrict__ bias,
                               float* __restrict__ C,
                               int M, int Ncols) {
    constexpr int K  = 128;
    constexpr int BM = 64, BN = 64, BK = 16;
    __shared__ float As[BK][BM + 4];
    __shared__ float Bs[BK][BN + 4];

    const int tid = threadIdx.x;
    const int bm = blockIdx.y * BM;
    const int bn = blockIdx.x * BN;
    const int tx = tid & 15;
    const int ty = tid >> 4;

    float acc[4][4] = {};

    for (int k0 = 0; k0 < K; k0 += BK) {
        {
            const int arow = tid >> 2;
            const int acol = (tid & 3) << 2;
            float4 av = make_float4(0.f, 0.f, 0.f, 0.f);
            const int gr = bm + arow;
            if (gr < M)
                av = *(const float4*)(A + (size_t)gr * K + k0 + acol);
            As[acol + 0][arow] = av.x;
            As[acol + 1][arow] = av.y;
            As[acol + 2][arow] = av.z;
            As[acol + 3][arow] = av.w;
        }
        {
            const int brow = tid >> 4;
            const int bcol = (tid & 15) << 2;
            const int gc = bn + bcol;
            Bs[brow][bcol + 0] = (gc + 0 < Ncols) ? B[(size_t)(k0 + brow) * Ncols + gc + 0] : 0.f;
            Bs[brow][bcol + 1] = (gc + 1 < Ncols) ? B[(size_t)(k0 + brow) * Ncols + gc + 1] : 0.f;
            Bs[brow][bcol + 2] = (gc + 2 < Ncols) ? B[(size_t)(k0 + brow) * Ncols + gc + 2] : 0.f;
            Bs[brow][bcol + 3] = (gc + 3 < Ncols) ? B[(size_t)(k0 + brow) * Ncols + gc + 3] : 0.f;
        }
        __syncthreads();

        #pragma unroll
        for (int k = 0; k < BK; k++) {
            float4 a = *(const float4*)(&As[k][ty << 2]);
            float4 b = *(const float4*)(&Bs[k][tx << 2]);
            acc[0][0] += a.x * b.x; acc[0][1] += a.x * b.y;
            acc[0][2] += a.x * b.z; acc[0][3] += a.x * b.w;
            acc[1][0] += a.y * b.x; acc[1][1] += a.y * b.y;
            acc[1][2] += a.y * b.z; acc[1][3] += a.y * b.w;
            acc[2][0] += a.z * b.x; acc[2][1] += a.z * b.y;
            acc[2][2] += a.z * b.z; acc[2][3] += a.z * b.w;
            acc[3][0] += a.w * b.x; acc[3][1] += a.w * b.y;
            acc[3][2] += a.w * b.z; acc[3][3] += a.w * b.w;
        }
        __syncthreads();
    }

    float bv[4] = {0.f, 0.f, 0.f, 0.f};
    #pragma unroll
    for (int j = 0; j < 4; j++) {
        int c = bn + (tx << 2) + j;
        bv[j] = (c < Ncols) ? bias[c] : 0.f;
    }
    #pragma unroll
    for (int i = 0; i < 4; i++) {
        int r = bm + (ty << 2) + i;
        if (r >= M) continue;
        #pragma unroll
        for (int j = 0; j < 4; j++) {
            int c = bn + (tx << 2) + j;
            if (c >= Ncols) continue;
            C[(size_t)r * Ncols + c] = acc[i][j] + bv[j];
        }
    }
}

// ---------------- edge scatter: one warp per edge, float4 atomics --------
__global__ void scatter_kernel(const int* __restrict__ src,
                               const int* __restrict__ dst,
                               const float* __restrict__ ew,
                               const float* __restrict__ xw,
                               float* __restrict__ agg) {
    int warp = (blockIdx.x * blockDim.x + threadIdx.x) >> 5;
    int lane = threadIdx.x & 31;
    if (warp >= EE) return;
    int s = src[warp];
    int d = dst[warp];
    float norm = g_dinv[s] * ew[warp] * g_dinv[d];
    float4 v = ((const float4*)(xw + (size_t)s * FH))[lane];
    v.x *= norm; v.y *= norm; v.z *= norm; v.w *= norm;
    atomicAdd((float4*)(agg + (size_t)d * FH + (lane << 2)), v);
}

// ---------------- bias + relu: xh = relu(agg + b) ----------------
__global__ void bias_relu_kernel(const float* __restrict__ agg,
                                 float* __restrict__ xh,
                                 const float* __restrict__ b) {
    size_t idx = (size_t)blockIdx.x * blockDim.x + threadIdx.x;
    if (idx >= (size_t)NN * FH) return;
    int f = (int)(idx & (FH - 1));
    xh[idx] = fmaxf(agg[idx] + b[f], 0.f);
}

// ---------------- host orchestration ----------------
extern "C" void kernel_launch(void* const* d_in, const int* in_sizes, int n_in,
                              void* d_out, int out_size) {
    const float* x     = (const float*)d_in[0];
    const int*   ei    = (const int*)  d_in[1];
    const float* ew    = (const float*)d_in[2];
    const float* h0    = (const float*)d_in[3];
    const float* linW  = (const float*)d_in[4];
    const float* linB  = (const float*)d_in[5];
    const float* convW = (const float*)d_in[6];
    const float* convB = (const float*)d_in[7];
    const float* Wih   = (const float*)d_in[8];
    const float* Whh   = (const float*)d_in[9];
    const float* bih   = (const float*)d_in[10];
    const float* bhh   = (const float*)d_in[11];
    const float* fcW   = (const float*)d_in[12];
    const float* fcB   = (const float*)d_in[13];
    float* out = (float*)d_out;

    const int* src = ei;
    const int* dst = ei + EE;

    static bool s_attr_done = false;
    if (!s_attr_done) {
        cudaFuncSetAttribute(gemm_tf32_kernel<true, true, false>,
                             cudaFuncAttributeMaxDynamicSharedMemorySize, GEMM_SMEM_BYTES);
        cudaFuncSetAttribute(gemm_tf32_kernel<false, false, true>,
                             cudaFuncAttributeMaxDynamicSharedMemorySize, GEMM_SMEM_BYTES);
        cudaFuncSetAttribute(gru_fused_kernel,
                             cudaFuncAttributeMaxDynamicSharedMemorySize, GRU_SMEM_BYTES);
        s_attr_done = true;
    }

    float *p_xh, *p_xw, *p_h, *p_agg;
    cudaGetSymbolAddress((void**)&p_xh,  g_xh);
    cudaGetSymbolAddress((void**)&p_xw,  g_xw);
    cudaGetSymbolAddress((void**)&p_h,   g_h);
    cudaGetSymbolAddress((void**)&p_agg, g_agg);

    const size_t NF = (size_t)NN * FH;
    const int EB = 256;
    const int NB = (NN + 127) / 128;   // 782

    const dim3 blk512(512);
    const dim3 grid128(1, NB);

    // degree + normalization
    init_deg_kernel<<<(NN + 255) / 256, 256>>>();
    accum_deg_kernel<<<(EE + EB - 1) / EB, EB>>>(dst, ew);
    dinv_kernel<<<(NN + 255) / 256, 256>>>();

    // xh = relu(x @ linW + linB)
    gemm_tf32_kernel<true, true, false><<<grid128, blk512, GEMM_SMEM_BYTES>>>(
        x, linW, linB, p_xh, nullptr, NN, FH);

    // h = GRU(xh, h0)  -- fully fused
    gru_fused_kernel<<<NB, blk512, GRU_SMEM_BYTES>>>(
        p_xh, h0, Wih, Whh, bih, bhh, p_h, NN);

    for (int l = 0; l < LL; l++) {
        const float* W = convW + (size_t)l * FH * FH;
        const float* b = convB + (size_t)l * FH;
        // xw = xh @ W ; agg = xw * dinv^2 (fused self-loop init)
        gemm_tf32_kernel<false, false, true><<<grid128, blk512, GEMM_SMEM_BYTES>>>(
            p_xh, W, nullptr, p_xw, p_agg, NN, FH);
        // edge scatter into agg (float4 vector atomics)
        scatter_kernel<<<(EE * 32 + 255) / 256, 256>>>(src, dst, ew, p_xw, p_agg);
        // xh = relu(agg + b)
        bias_relu_kernel<<<(int)((NF + 255) / 256), 256>>>(p_agg, p_xh, b);
        // h = GRU(xh, h)  -- fused, in-place on h (CTA-local rows only)
        gru_fused_kernel<<<NB, blk512, GRU_SMEM_BYTES>>>(
            p_xh, p_h, Wih, Whh, bih, bhh, p_h, NN);
    }

    // out = h @ fcW + fcB (fp32 fallback: Ncols=40)
    {
        dim3 grid((CC + 63) / 64, (NN + 63) / 64);
        gemm_fc_kernel<<<grid, 256>>>(p_h, fcW, fcB, out, NN, CC);
    }
}

// round 13
// speedup vs baseline: 2.9259x; 1.3506x over previous
#include <cuda_runtime.h>
#include <cstdint>

// Problem constants (fixed by reference)
#define NN   100000
#define EE   1600000
#define FH   128      // F_IN == H == HG
#define H3   384      // 3*HG
#define CC   40
#define LL   3

// ---------------- scratch (device globals; no allocation allowed) ----------
__device__ float g_xh[(size_t)NN * FH];
__device__ float g_xw[(size_t)NN * FH];
__device__ float g_h [(size_t)NN * FH];
__device__ float g_deg [NN];
__device__ float g_dinv[NN];
// CSR (dst-sorted edge list, rebuilt every call)
__device__ int   g_cnt[NN];          // histogram, then cursor
__device__ int   g_rowstart[NN + 1];
__device__ int   g_blocksum[256];
__device__ int   g_esrc[EE];
__device__ float g_ew2[EE];

#define SCAN_B 512
#define NBLK ((NN + SCAN_B - 1) / SCAN_B)   // 196

// ---------------- degree + histogram ----------------
__global__ void init_deg_kernel() {
    int i = blockIdx.x * blockDim.x + threadIdx.x;
    if (i < NN) { g_deg[i] = 1.0f; g_cnt[i] = 0; }   // self-loop weight 1
}

__global__ void accum_deg_kernel(const int* __restrict__ dst,
                                 const float* __restrict__ ew) {
    int e = blockIdx.x * blockDim.x + threadIdx.x;
    if (e < EE) {
        int d = dst[e];
        atomicAdd(&g_deg[d], ew[e]);
        atomicAdd(&g_cnt[d], 1);
    }
}

__global__ void dinv_kernel() {
    int i = blockIdx.x * blockDim.x + threadIdx.x;
    if (i < NN) g_dinv[i] = rsqrtf(g_deg[i]);   // deg >= 1 always
}

// ---------------- exclusive scan over g_cnt -> g_rowstart ----------------
__global__ void scan1_kernel() {
    __shared__ int sh[SCAN_B];
    int b = blockIdx.x, t = threadIdx.x;
    int i = b * SCAN_B + t;
    int v = (i < NN) ? g_cnt[i] : 0;
    sh[t] = v;
    __syncthreads();
    #pragma unroll
    for (int off = 1; off < SCAN_B; off <<= 1) {
        int x = (t >= off) ? sh[t - off] : 0;
        __syncthreads();
        sh[t] += x;
        __syncthreads();
    }
    if (i < NN) g_rowstart[i] = sh[t] - v;            // block-local exclusive
    if (t == SCAN_B - 1) g_blocksum[b] = sh[t];       // block total
}

__global__ void scan2_kernel() {
    __shared__ int sh[256];
    int t = threadIdx.x;   // 256 threads, NBLK=196
    int v = (t < NBLK) ? g_blocksum[t] : 0;
    sh[t] = v;
    __syncthreads();
    #pragma unroll
    for (int off = 1; off < 256; off <<= 1) {
        int x = (t >= off) ? sh[t - off] : 0;
        __syncthreads();
        sh[t] += x;
        __syncthreads();
    }
    if (t < NBLK) g_blocksum[t] = sh[t] - v;          // exclusive
}

__global__ void scan3_kernel() {
    int i = blockIdx.x * blockDim.x + threadIdx.x;
    if (i < NN) {
        int v = g_rowstart[i] + g_blocksum[i / SCAN_B];
        g_rowstart[i] = v;
        g_cnt[i] = v;      // cursor for fill
    }
    if (i == 0) g_rowstart[NN] = EE;
}

// ---------------- fill CSR: src + precomputed norm ----------------
__global__ void fill_kernel(const int* __restrict__ src,
                            const int* __restrict__ dst,
                            const float* __restrict__ ew) {
    int e = blockIdx.x * blockDim.x + threadIdx.x;
    if (e >= EE) return;
    int s = src[e], d = dst[e];
    int pos = atomicAdd(&g_cnt[d], 1);
    g_esrc[pos] = s;
    g_ew2[pos] = g_dinv[s] * ew[e] * g_dinv[d];
}

// ---------------- gather aggregation: warp per dst node, NO atomics ------
// xh[d] = relu( xw[d]*dinv[d]^2 + sum_e xw[src_e]*norm_e + bias )
__global__ void gather_agg_kernel(const float* __restrict__ xw,
                                  const float* __restrict__ bias,
                                  float* __restrict__ xh) {
    int d = (blockIdx.x * blockDim.x + threadIdx.x) >> 5;
    int lane = threadIdx.x & 31;
    if (d >= NN) return;
    float di = g_dinv[d];
    float sw = di * di;
    float4 acc = ((const float4*)(xw + (size_t)d * FH))[lane];
    acc.x *= sw; acc.y *= sw; acc.z *= sw; acc.w *= sw;
    int beg = g_rowstart[d], end = g_rowstart[d + 1];
    int i = beg;
    for (; i + 1 < end; i += 2) {                 // MLP=2
        int s0 = g_esrc[i], s1 = g_esrc[i + 1];
        float w0 = g_ew2[i], w1 = g_ew2[i + 1];
        float4 v0 = ((const float4*)(xw + (size_t)s0 * FH))[lane];
        float4 v1 = ((const float4*)(xw + (size_t)s1 * FH))[lane];
        acc.x += v0.x * w0 + v1.x * w1;
        acc.y += v0.y * w0 + v1.y * w1;
        acc.z += v0.z * w0 + v1.z * w1;
        acc.w += v0.w * w0 + v1.w * w1;
    }
    if (i < end) {
        int s = g_esrc[i];
        float w = g_ew2[i];
        float4 v = ((const float4*)(xw + (size_t)s * FH))[lane];
        acc.x += v.x * w; acc.y += v.y * w;
        acc.z += v.z * w; acc.w += v.w * w;
    }
    float4 b = ((const float4*)bias)[lane];
    acc.x = fmaxf(acc.x + b.x, 0.f);
    acc.y = fmaxf(acc.y + b.y, 0.f);
    acc.z = fmaxf(acc.z + b.z, 0.f);
    acc.w = fmaxf(acc.w + b.w, 0.f);
    ((float4*)(xh + (size_t)d * FH))[lane] = acc;
}

// ---------------- shared MMA machinery (measured-good from R8) ------------
#define TS 132

__device__ __forceinline__ float to_tf32(float v) {
    uint32_t o;
    asm volatile("cvt.rna.tf32.f32 %0, %1;" : "=r"(o) : "f"(v));
    return __uint_as_float(o);
}

__device__ __forceinline__ void ldsm4(uint32_t* r, uint32_t addr) {
    asm volatile(
        "ldmatrix.sync.aligned.m8n8.x4.shared.b16 {%0,%1,%2,%3}, [%4];"
        : "=r"(r[0]), "=r"(r[1]), "=r"(r[2]), "=r"(r[3]) : "r"(addr));
}

__device__ __forceinline__ void mma_tf32(float* d, const uint32_t* a,
                                         uint32_t b0, uint32_t b1) {
    asm volatile(
        "mma.sync.aligned.m16n8k8.row.col.f32.tf32.tf32.f32 "
        "{%0,%1,%2,%3}, {%4,%5,%6,%7}, {%8,%9}, {%0,%1,%2,%3};\n"
        : "+f"(d[0]), "+f"(d[1]), "+f"(d[2]), "+f"(d[3])
        : "r"(a[0]), "r"(a[1]), "r"(a[2]), "r"(a[3]), "r"(b0), "r"(b1));
}

__device__ __forceinline__ void mma_pass(uint32_t aA0, uint32_t aA1,
                                         uint32_t bA0, uint32_t bA1,
                                         float acc[2][4][4]) {
    #pragma unroll
    for (int mi = 0; mi < 2; mi++)
        #pragma unroll
        for (int ni = 0; ni < 4; ni++)
            #pragma unroll
            for (int j = 0; j < 4; j++) acc[mi][ni][j] = 0.f;
    #pragma unroll
    for (int ks = 0; ks < 16; ks++) {
        uint32_t a0[4], a1[4], b01[4], b23[4];
        uint32_t ko = (uint32_t)ks * 32;
        ldsm4(a0,  aA0 + ko);
        ldsm4(a1,  aA1 + ko);
        ldsm4(b01, bA0 + ko);
        ldsm4(b23, bA1 + ko);
        mma_tf32(acc[0][0], a0, b01[0], b01[1]);
        mma_tf32(acc[0][1], a0, b01[2], b01[3]);
        mma_tf32(acc[0][2], a0, b23[0], b23[1]);
        mma_tf32(acc[0][3], a0, b23[2], b23[3]);
        mma_tf32(acc[1][0], a1, b01[0], b01[1]);
        mma_tf32(acc[1][1], a1, b01[2], b01[3]);
        mma_tf32(acc[1][2], a1, b23[0], b23[1]);
        mma_tf32(acc[1][3], a1, b23[2], b23[3]);
    }
}

__device__ __forceinline__ float sigm(float x) {
    return 1.f / (1.f + expf(-x));
}

// =====================================================================
// TF32 GEMM (lin / conv): C[M,Ncols] = A[M,128] * B[128,Ncols] (+bias)(+relu)
// =====================================================================
#define GEMM_SMEM_BYTES (2 * 128 * TS * 4)   // 135168 B

template<bool BIAS, bool RELU>
__global__ __launch_bounds__(512, 1)
void gemm_tf32_kernel(const float* __restrict__ A,
                      const float* __restrict__ B,
                      const float* __restrict__ bias,
                      float* __restrict__ C,
                      int M, int Ncols) {
    extern __shared__ float smem[];
    float* As = smem;             // [128][TS]
    float* Bs = smem + 128 * TS;  // [128][TS]

    const int tid  = threadIdx.x;
    const int lane = tid & 31;
    const int wid  = tid >> 5;
    const int lr   = lane >> 2;
    const int lc   = lane & 3;
    const int bm = blockIdx.y * 128;
    const int bn = blockIdx.x * 128;

    #pragma unroll
    for (int it = 0; it < 8; it++) {
        int i = it * 512 + tid;
        int m = i >> 5;
        int q = (i & 31) << 2;
        int gr = bm + m;
        float4 v = make_float4(0.f, 0.f, 0.f, 0.f);
        if (gr < M) v = *(const float4*)(A + (size_t)gr * 128 + q);
        *(float4*)(As + m * TS + q) = make_float4(to_tf32(v.x), to_tf32(v.y),
                                                  to_tf32(v.z), to_tf32(v.w));
    }
    // transpose fill: Bs[n][k] = B[k][bn+n]
    #pragma unroll
    for (int it = 0; it < 8; it++) {
        int i = it * 512 + tid;
        int k = i >> 5;
        int p = (i & 31) << 2;
        float4 v = *(const float4*)(B + (size_t)k * Ncols + bn + p);
        Bs[(p + 0) * TS + k] = to_tf32(v.x);
        Bs[(p + 1) * TS + k] = to_tf32(v.y);
        Bs[(p + 2) * TS + k] = to_tf32(v.z);
        Bs[(p + 3) * TS + k] = to_tf32(v.w);
    }
    __syncthreads();

    const int wtm = wid & 3;
    const int wtn = wid >> 2;
    uint32_t as_base = (uint32_t)__cvta_generic_to_shared(As);
    uint32_t bs_base = (uint32_t)__cvta_generic_to_shared(Bs);
    int arow = (lane & 7) + ((lane >> 3) & 1) * 8;
    int acol = (lane >> 4) << 2;
    int brow = (lane & 7) + ((lane >> 4) << 3);
    int bcol = ((lane >> 3) & 1) << 2;
    uint32_t aA0 = as_base + (((wtm * 32 +  0 + arow) * TS + acol) << 2);
    uint32_t aA1 = as_base + (((wtm * 32 + 16 + arow) * TS + acol) << 2);
    uint32_t bA0 = bs_base + (((wtn * 32 +  0 + brow) * TS + bcol) << 2);
    uint32_t bA1 = bs_base + (((wtn * 32 + 16 + brow) * TS + bcol) << 2);

    float acc[2][4][4];
    mma_pass(aA0, aA1, bA0, bA1, acc);

    #pragma unroll
    for (int mi = 0; mi < 2; mi++) {
        int r0 = bm + wtm * 32 + mi * 16 + lr;
        int r1 = r0 + 8;
        #pragma unroll
        for (int ni = 0; ni < 4; ni++) {
            int c0 = bn + wtn * 32 + ni * 8 + (lc << 1);
            float b0 = 0.f, b1 = 0.f;
            if (BIAS) { b0 = bias[c0]; b1 = bias[c0 + 1]; }
            float v0 = acc[mi][ni][0] + b0;
            float v1 = acc[mi][ni][1] + b1;
            float v2 = acc[mi][ni][2] + b0;
            float v3 = acc[mi][ni][3] + b1;
            if (RELU) {
                v0 = fmaxf(v0, 0.f); v1 = fmaxf(v1, 0.f);
                v2 = fmaxf(v2, 0.f); v3 = fmaxf(v3, 0.f);
            }
            if (r0 < M) *(float2*)(C + (size_t)r0 * Ncols + c0) = make_float2(v0, v1);
            if (r1 < M) *(float2*)(C + (size_t)r1 * Ncols + c0) = make_float2(v2, v3);
        }
    }
}

// =====================================================================
// FUSED GRU (measured-good from R12): h' = GRU(xh, h) in ONE kernel.
// =====================================================================
#define GRU_SMEM_BYTES (3 * 128 * TS * 4 + 2 * H3 * 4)   // 205824 B

__device__ __forceinline__ void load_w(float* Ws, const float* __restrict__ W,
                                       int tid) {
    #pragma unroll
    for (int it = 0; it < 8; it++) {
        int i = it * 512 + tid;
        int n = i >> 5;
        int q = (i & 31) << 2;
        float4 v = *(const float4*)(W + (size_t)n * 128 + q);
        *(float4*)(Ws + n * TS + q) = make_float4(to_tf32(v.x), to_tf32(v.y),
                                                  to_tf32(v.z), to_tf32(v.w));
    }
}

__global__ __launch_bounds__(512, 1)
void gru_fused_kernel(const float* __restrict__ xh,
                      const float* __restrict__ hin,
                      const float* __restrict__ Wih,
                      const float* __restrict__ Whh,
                      const float* __restrict__ bih,
                      const float* __restrict__ bhh,
                      float* __restrict__ hout,
                      int M) {
    extern __shared__ float smem[];
    float* Axh = smem;                 // [128][TS] tf32
    float* Ah  = smem + 128 * TS;      // [128][TS] raw fp32
    float* Ws  = smem + 256 * TS;      // [128][TS] weight slice
    float* bi_s = smem + 384 * TS;     // [384]
    float* bh_s = bi_s + H3;           // [384]

    const int tid  = threadIdx.x;
    const int lane = tid & 31;
    const int wid  = tid >> 5;
    const int lr   = lane >> 2;
    const int lc   = lane & 3;
    const int bm = blockIdx.x * 128;

    #pragma unroll
    for (int it = 0; it < 8; it++) {
        int i = it * 512 + tid;
        int m = i >> 5;
        int q = (i & 31) << 2;
        int gr = bm + m;
        float4 vx = make_float4(0.f, 0.f, 0.f, 0.f);
        float4 vh = make_float4(0.f, 0.f, 0.f, 0.f);
        if (gr < M) {
            vx = *(const float4*)(xh  + (size_t)gr * 128 + q);
            vh = *(const float4*)(hin + (size_t)gr * 128 + q);
        }
        *(float4*)(Axh + m * TS + q) = make_float4(to_tf32(vx.x), to_tf32(vx.y),
                                                   to_tf32(vx.z), to_tf32(vx.w));
        *(float4*)(Ah + m * TS + q) = vh;
    }
    if (tid < H3) { bi_s[tid] = bih[tid]; bh_s[tid] = bhh[tid]; }

    const int wtm = wid & 3;
    const int wtn = wid >> 2;
    int arow = (lane & 7) + ((lane >> 3) & 1) * 8;
    int acol = (lane >> 4) << 2;
    int brow = (lane & 7) + ((lane >> 4) << 3);
    int bcol = ((lane >> 3) & 1) << 2;
    uint32_t axh_b = (uint32_t)__cvta_generic_to_shared(Axh);
    uint32_t ah_b  = (uint32_t)__cvta_generic_to_shared(Ah);
    uint32_t ws_b  = (uint32_t)__cvta_generic_to_shared(Ws);
    uint32_t aO0 = ((wtm * 32 +  0 + arow) * TS + acol) << 2;
    uint32_t aO1 = ((wtm * 32 + 16 + arow) * TS + acol) << 2;
    uint32_t bO0 = ((wtn * 32 +  0 + brow) * TS + bcol) << 2;
    uint32_t bO1 = ((wtn * 32 + 16 + brow) * TS + bcol) << 2;

    float gi[2][4][4], gh[2][4][4], ra[2][4][4], na[2][4][4];

    // ======== gate r (slice 0) ========
    load_w(Ws, Wih, tid);
    __syncthreads();
    mma_pass(axh_b + aO0, axh_b + aO1, ws_b + bO0, ws_b + bO1, gi);
    __syncthreads();
    load_w(Ws, Whh, tid);
    __syncthreads();
    mma_pass(ah_b + aO0, ah_b + aO1, ws_b + bO0, ws_b + bO1, gh);
    #pragma unroll
    for (int mi = 0; mi < 2; mi++)
        #pragma unroll
        for (int ni = 0; ni < 4; ni++) {
            int col = wtn * 32 + ni * 8 + (lc << 1);
            float bs0 = bi_s[col] + bh_s[col];
            float bs1 = bi_s[col + 1] + bh_s[col + 1];
            ra[mi][ni][0] = sigm(gi[mi][ni][0] + gh[mi][ni][0] + bs0);
            ra[mi][ni][1] = sigm(gi[mi][ni][1] + gh[mi][ni][1] + bs1);
            ra[mi][ni][2] = sigm(gi[mi][ni][2] + gh[mi][ni][2] + bs0);
            ra[mi][ni][3] = sigm(gi[mi][ni][3] + gh[mi][ni][3] + bs1);
        }

    // ======== gate n (slice 2) ========
    __syncthreads();
    load_w(Ws, Wih + 2 * 128 * 128, tid);
    __syncthreads();
    mma_pass(axh_b + aO0, axh_b + aO1, ws_b + bO0, ws_b + bO1, gi);
    __syncthreads();
    load_w(Ws, Whh + 2 * 128 * 128, tid);
    __syncthreads();
    mma_pass(ah_b + aO0, ah_b + aO1, ws_b + bO0, ws_b + bO1, gh);
    #pragma unroll
    for (int mi = 0; mi < 2; mi++)
        #pragma unroll
        for (int ni = 0; ni < 4; ni++) {
            int col = wtn * 32 + ni * 8 + (lc << 1);
            float bi0 = bi_s[256 + col], bi1 = bi_s[256 + col + 1];
            float bh0 = bh_s[256 + col], bh1 = bh_s[256 + col + 1];
            na[mi][ni][0] = tanhf(gi[mi][ni][0] + bi0 + ra[mi][ni][0] * (gh[mi][ni][0] + bh0));
            na[mi][ni][1] = tanhf(gi[mi][ni][1] + bi1 + ra[mi][ni][1] * (gh[mi][ni][1] + bh1));
            na[mi][ni][2] = tanhf(gi[mi][ni][2] + bi0 + ra[mi][ni][2] * (gh[mi][ni][2] + bh0));
            na[mi][ni][3] = tanhf(gi[mi][ni][3] + bi1 + ra[mi][ni][3] * (gh[mi][ni][3] + bh1));
        }

    // ======== gate z (slice 1) + blend + store ========
    __syncthreads();
    load_w(Ws, Wih + 128 * 128, tid);
    __syncthreads();
    mma_pass(axh_b + aO0, axh_b + aO1, ws_b + bO0, ws_b + bO1, gi);
    __syncthreads();
    load_w(Ws, Whh + 128 * 128, tid);
    __syncthreads();
    mma_pass(ah_b + aO0, ah_b + aO1, ws_b + bO0, ws_b + bO1, gh);
    #pragma unroll
    for (int mi = 0; mi < 2; mi++) {
        int row0 = wtm * 32 + mi * 16 + lr;
        int row1 = row0 + 8;
        int gr0 = bm + row0, gr1 = bm + row1;
        #pragma unroll
        for (int ni = 0; ni < 4; ni++) {
            int col = wtn * 32 + ni * 8 + (lc << 1);
            float bs0 = bi_s[128 + col] + bh_s[128 + col];
            float bs1 = bi_s[128 + col + 1] + bh_s[128 + col + 1];
            float z0 = sigm(gi[mi][ni][0] + gh[mi][ni][0] + bs0);
            float z1 = sigm(gi[mi][ni][1] + gh[mi][ni][1] + bs1);
            float z2 = sigm(gi[mi][ni][2] + gh[mi][ni][2] + bs0);
            float z3 = sigm(gi[mi][ni][3] + gh[mi][ni][3] + bs1);
            float2 h0v = *(float2*)(Ah + row0 * TS + col);
            float2 h1v = *(float2*)(Ah + row1 * TS + col);
            float v0 = (1.f - z0) * na[mi][ni][0] + z0 * h0v.x;
            float v1 = (1.f - z1) * na[mi][ni][1] + z1 * h0v.y;
            float v2 = (1.f - z2) * na[mi][ni][2] + z2 * h1v.x;
            float v3 = (1.f - z3) * na[mi][ni][3] + z3 * h1v.y;
            if (gr0 < M) *(float2*)(hout + (size_t)gr0 * 128 + col) = make_float2(v0, v1);
            if (gr1 < M) *(float2*)(hout + (size_t)gr1 * 128 + col) = make_float2(v2, v3);
        }
    }
}

// ---------------- fp32 fallback GEMM (fc, Ncols=40) ----------------------
__global__ void gemm_fc_kernel(const float* __restrict__ A,
                               const float* __restrict__ B,
                               const float* __restrict__ bias,
                               float* __restrict__ C,
                               int M, int Ncols) {
    constexpr int K  = 128;
    constexpr int BM = 64, BN = 64, BK = 16;
    __shared__ float As[BK][BM + 4];
    __shared__ float Bs[BK][BN + 4];

    const int tid = threadIdx.x;
    const int bm = blockIdx.y * BM;
    const int bn = blockIdx.x * BN;
    const int tx = tid & 15;
    const int ty = tid >> 4;

    float acc[4][4] = {};

    for (int k0 = 0; k0 < K; k0 += BK) {
        {
            const int arow = tid >> 2;
            const int acol = (tid & 3) << 2;
            float4 av = make_float4(0.f, 0.f, 0.f, 0.f);
            const int gr = bm + arow;
            if (gr < M)
                av = *(const float4*)(A + (size_t)gr * K + k0 + acol);
            As[acol + 0][arow] = av.x;
            As[acol + 1][arow] = av.y;
            As[acol + 2][arow] = av.z;
            As[acol + 3][arow] = av.w;
        }
        {
            const int brow = tid >> 4;
            const int bcol = (tid & 15) << 2;
            const int gc = bn + bcol;
            Bs[brow][bcol + 0] = (gc + 0 < Ncols) ? B[(size_t)(k0 + brow) * Ncols + gc + 0] : 0.f;
            Bs[brow][bcol + 1] = (gc + 1 < Ncols) ? B[(size_t)(k0 + brow) * Ncols + gc + 1] : 0.f;
            Bs[brow][bcol + 2] = (gc + 2 < Ncols) ? B[(size_t)(k0 + brow) * Ncols + gc + 2] : 0.f;
            Bs[brow][bcol + 3] = (gc + 3 < Ncols) ? B[(size_t)(k0 + brow) * Ncols + gc + 3] : 0.f;
        }
        __syncthreads();

        #pragma unroll
        for (int k = 0; k < BK; k++) {
            float4 a = *(const float4*)(&As[k][ty << 2]);
            float4 b = *(const float4*)(&Bs[k][tx << 2]);
            acc[0][0] += a.x * b.x; acc[0][1] += a.x * b.y;
            acc[0][2] += a.x * b.z; acc[0][3] += a.x * b.w;
            acc[1][0] += a.y * b.x; acc[1][1] += a.y * b.y;
            acc[1][2] += a.y * b.z; acc[1][3] += a.y * b.w;
            acc[2][0] += a.z * b.x; acc[2][1] += a.z * b.y;
            acc[2][2] += a.z * b.z; acc[2][3] += a.z * b.w;
            acc[3][0] += a.w * b.x; acc[3][1] += a.w * b.y;
            acc[3][2] += a.w * b.z; acc[3][3] += a.w * b.w;
        }
        __syncthreads();
    }

    float bv[4] = {0.f, 0.f, 0.f, 0.f};
    #pragma unroll
    for (int j = 0; j < 4; j++) {
        int c = bn + (tx << 2) + j;
        bv[j] = (c < Ncols) ? bias[c] : 0.f;
    }
    #pragma unroll
    for (int i = 0; i < 4; i++) {
        int r = bm + (ty << 2) + i;
        if (r >= M) continue;
        #pragma unroll
        for (int j = 0; j < 4; j++) {
            int c = bn + (tx << 2) + j;
            if (c >= Ncols) continue;
            C[(size_t)r * Ncols + c] = acc[i][j] + bv[j];
        }
    }
}

// ---------------- host orchestration ----------------
extern "C" void kernel_launch(void* const* d_in, const int* in_sizes, int n_in,
                              void* d_out, int out_size) {
    const float* x     = (const float*)d_in[0];
    const int*   ei    = (const int*)  d_in[1];
    const float* ew    = (const float*)d_in[2];
    const float* h0    = (const float*)d_in[3];
    const float* linW  = (const float*)d_in[4];
    const float* linB  = (const float*)d_in[5];
    const float* convW = (const float*)d_in[6];
    const float* convB = (const float*)d_in[7];
    const float* Wih   = (const float*)d_in[8];
    const float* Whh   = (const float*)d_in[9];
    const float* bih   = (const float*)d_in[10];
    const float* bhh   = (const float*)d_in[11];
    const float* fcW   = (const float*)d_in[12];
    const float* fcB   = (const float*)d_in[13];
    float* out = (float*)d_out;

    const int* src = ei;
    const int* dst = ei + EE;

    static bool s_attr_done = false;
    if (!s_attr_done) {
        cudaFuncSetAttribute(gemm_tf32_kernel<true, true>,
                             cudaFuncAttributeMaxDynamicSharedMemorySize, GEMM_SMEM_BYTES);
        cudaFuncSetAttribute(gemm_tf32_kernel<false, false>,
                             cudaFuncAttributeMaxDynamicSharedMemorySize, GEMM_SMEM_BYTES);
        cudaFuncSetAttribute(gru_fused_kernel,
                             cudaFuncAttributeMaxDynamicSharedMemorySize, GRU_SMEM_BYTES);
        s_attr_done = true;
    }

    float *p_xh, *p_xw, *p_h;
    cudaGetSymbolAddress((void**)&p_xh, g_xh);
    cudaGetSymbolAddress((void**)&p_xw, g_xw);
    cudaGetSymbolAddress((void**)&p_h,  g_h);

    const int EB = 256;
    const int NB = (NN + 127) / 128;   // 782

    const dim3 blk512(512);
    const dim3 grid128(1, NB);

    // ---- degree + histogram + CSR build (once, reused 3x) ----
    init_deg_kernel<<<(NN + 255) / 256, 256>>>();
    accum_deg_kernel<<<(EE + EB - 1) / EB, EB>>>(dst, ew);
    dinv_kernel<<<(NN + 255) / 256, 256>>>();
    scan1_kernel<<<NBLK, SCAN_B>>>();
    scan2_kernel<<<1, 256>>>();
    scan3_kernel<<<(NN + 255) / 256, 256>>>();
    fill_kernel<<<(EE + EB - 1) / EB, EB>>>(src, dst, ew);

    // xh = relu(x @ linW + linB)
    gemm_tf32_kernel<true, true><<<grid128, blk512, GEMM_SMEM_BYTES>>>(
        x, linW, linB, p_xh, NN, FH);

    // h = GRU(xh, h0)
    gru_fused_kernel<<<NB, blk512, GRU_SMEM_BYTES>>>(
        p_xh, h0, Wih, Whh, bih, bhh, p_h, NN);

    for (int l = 0; l < LL; l++) {
        const float* W = convW + (size_t)l * FH * FH;
        const float* b = convB + (size_t)l * FH;
        // xw = xh @ W
        gemm_tf32_kernel<false, false><<<grid128, blk512, GEMM_SMEM_BYTES>>>(
            p_xh, W, nullptr, p_xw, NN, FH);
        // xh = relu(selfloop + gather-agg + bias)   [no atomics]
        gather_agg_kernel<<<(NN * 32 + 255) / 256, 256>>>(p_xw, b, p_xh);
        // h = GRU(xh, h)
        gru_fused_kernel<<<NB, blk512, GRU_SMEM_BYTES>>>(
            p_xh, p_h, Wih, Whh, bih, bhh, p_h, NN);
    }

    // out = h @ fcW + fcB
    {
        dim3 grid((CC + 63) / 64, (NN + 63) / 64);
        gemm_fc_kernel<<<grid, 256>>>(p_h, fcW, fcB, out, NN, CC);
    }
}

// round 14
// speedup vs baseline: 3.0370x; 1.0380x over previous
#include <cuda_runtime.h>
#include <cstdint>

// Problem constants (fixed by reference)
#define NN   100000
#define EE   1600000
#define FH   128      // F_IN == H == HG
#define H3   384      // 3*HG
#define CC   40
#define LL   3

// ---------------- scratch (device globals; no allocation allowed) ----------
__device__ float g_xh[(size_t)NN * FH];
__device__ float g_xw[(size_t)NN * FH];
__device__ float g_h [(size_t)NN * FH];
__device__ float g_deg [NN];
__device__ float g_dinv[NN];
// CSR (dst-sorted edge list, rebuilt every call)
__device__ int   g_cnt[NN];          // histogram, then cursor
__device__ int   g_rowstart[NN + 1];
__device__ int   g_blocksum[256];
__device__ int   g_esrc[EE];
__device__ float g_ew2[EE];

#define SCAN_B 512
#define NBLK ((NN + SCAN_B - 1) / SCAN_B)   // 196

// ---------------- degree + histogram ----------------
__global__ void init_deg_kernel() {
    int i = blockIdx.x * blockDim.x + threadIdx.x;
    if (i < NN) { g_deg[i] = 1.0f; g_cnt[i] = 0; }   // self-loop weight 1
}

__global__ void accum_deg_kernel(const int* __restrict__ dst,
                                 const float* __restrict__ ew) {
    int e = blockIdx.x * blockDim.x + threadIdx.x;
    if (e < EE) {
        int d = dst[e];
        atomicAdd(&g_deg[d], ew[e]);
        atomicAdd(&g_cnt[d], 1);
    }
}

__global__ void dinv_kernel() {
    int i = blockIdx.x * blockDim.x + threadIdx.x;
    if (i < NN) g_dinv[i] = rsqrtf(g_deg[i]);   // deg >= 1 always
}

// ---------------- exclusive scan over g_cnt -> g_rowstart ----------------
__global__ void scan1_kernel() {
    __shared__ int sh[SCAN_B];
    int b = blockIdx.x, t = threadIdx.x;
    int i = b * SCAN_B + t;
    int v = (i < NN) ? g_cnt[i] : 0;
    sh[t] = v;
    __syncthreads();
    #pragma unroll
    for (int off = 1; off < SCAN_B; off <<= 1) {
        int x = (t >= off) ? sh[t - off] : 0;
        __syncthreads();
        sh[t] += x;
        __syncthreads();
    }
    if (i < NN) g_rowstart[i] = sh[t] - v;            // block-local exclusive
    if (t == SCAN_B - 1) g_blocksum[b] = sh[t];       // block total
}

__global__ void scan2_kernel() {
    __shared__ int sh[256];
    int t = threadIdx.x;   // 256 threads, NBLK=196
    int v = (t < NBLK) ? g_blocksum[t] : 0;
    sh[t] = v;
    __syncthreads();
    #pragma unroll
    for (int off = 1; off < 256; off <<= 1) {
        int x = (t >= off) ? sh[t - off] : 0;
        __syncthreads();
        sh[t] += x;
        __syncthreads();
    }
    if (t < NBLK) g_blocksum[t] = sh[t] - v;          // exclusive
}

__global__ void scan3_kernel() {
    int i = blockIdx.x * blockDim.x + threadIdx.x;
    if (i < NN) {
        int v = g_rowstart[i] + g_blocksum[i / SCAN_B];
        g_rowstart[i] = v;
        g_cnt[i] = v;      // cursor for fill
    }
    if (i == 0) g_rowstart[NN] = EE;
}

// ---------------- fill CSR: src + precomputed norm ----------------
__global__ void fill_kernel(const int* __restrict__ src,
                            const int* __restrict__ dst,
                            const float* __restrict__ ew) {
    int e = blockIdx.x * blockDim.x + threadIdx.x;
    if (e >= EE) return;
    int s = src[e], d = dst[e];
    int pos = atomicAdd(&g_cnt[d], 1);
    g_esrc[pos] = s;
    g_ew2[pos] = g_dinv[s] * ew[e] * g_dinv[d];
}

// ---------------- gather aggregation: warp per dst node, NO atomics ------
// xh[d] = relu( xw[d]*dinv[d]^2 + sum_e xw[src_e]*norm_e + bias )
__global__ void gather_agg_kernel(const float* __restrict__ xw,
                                  const float* __restrict__ bias,
                                  float* __restrict__ xh) {
    int d = (blockIdx.x * blockDim.x + threadIdx.x) >> 5;
    int lane = threadIdx.x & 31;
    if (d >= NN) return;
    float di = g_dinv[d];
    float sw = di * di;
    float4 acc = ((const float4*)(xw + (size_t)d * FH))[lane];
    acc.x *= sw; acc.y *= sw; acc.z *= sw; acc.w *= sw;
    int beg = g_rowstart[d], end = g_rowstart[d + 1];
    int i = beg;
    for (; i + 3 < end; i += 4) {                 // MLP=4
        int s0 = g_esrc[i], s1 = g_esrc[i + 1];
        int s2 = g_esrc[i + 2], s3 = g_esrc[i + 3];
        float w0 = g_ew2[i], w1 = g_ew2[i + 1];
        float w2 = g_ew2[i + 2], w3 = g_ew2[i + 3];
        float4 v0 = ((const float4*)(xw + (size_t)s0 * FH))[lane];
        float4 v1 = ((const float4*)(xw + (size_t)s1 * FH))[lane];
        float4 v2 = ((const float4*)(xw + (size_t)s2 * FH))[lane];
        float4 v3 = ((const float4*)(xw + (size_t)s3 * FH))[lane];
        acc.x += v0.x * w0 + v1.x * w1 + v2.x * w2 + v3.x * w3;
        acc.y += v0.y * w0 + v1.y * w1 + v2.y * w2 + v3.y * w3;
        acc.z += v0.z * w0 + v1.z * w1 + v2.z * w2 + v3.z * w3;
        acc.w += v0.w * w0 + v1.w * w1 + v2.w * w2 + v3.w * w3;
    }
    for (; i < end; i++) {
        int s = g_esrc[i];
        float w = g_ew2[i];
        float4 v = ((const float4*)(xw + (size_t)s * FH))[lane];
        acc.x += v.x * w; acc.y += v.y * w;
        acc.z += v.z * w; acc.w += v.w * w;
    }
    float4 b = ((const float4*)bias)[lane];
    acc.x = fmaxf(acc.x + b.x, 0.f);
    acc.y = fmaxf(acc.y + b.y, 0.f);
    acc.z = fmaxf(acc.z + b.z, 0.f);
    acc.w = fmaxf(acc.w + b.w, 0.f);
    ((float4*)(xh + (size_t)d * FH))[lane] = acc;
}

// ---------------- shared MMA machinery (measured-good from R8) ------------
#define TS 132

__device__ __forceinline__ float to_tf32(float v) {
    uint32_t o;
    asm volatile("cvt.rna.tf32.f32 %0, %1;" : "=r"(o) : "f"(v));
    return __uint_as_float(o);
}

__device__ __forceinline__ void ldsm4(uint32_t* r, uint32_t addr) {
    asm volatile(
        "ldmatrix.sync.aligned.m8n8.x4.shared.b16 {%0,%1,%2,%3}, [%4];"
        : "=r"(r[0]), "=r"(r[1]), "=r"(r[2]), "=r"(r[3]) : "r"(addr));
}

__device__ __forceinline__ void mma_tf32(float* d, const uint32_t* a,
                                         uint32_t b0, uint32_t b1) {
    asm volatile(
        "mma.sync.aligned.m16n8k8.row.col.f32.tf32.tf32.f32 "
        "{%0,%1,%2,%3}, {%4,%5,%6,%7}, {%8,%9}, {%0,%1,%2,%3};\n"
        : "+f"(d[0]), "+f"(d[1]), "+f"(d[2]), "+f"(d[3])
        : "r"(a[0]), "r"(a[1]), "r"(a[2]), "r"(a[3]), "r"(b0), "r"(b1));
}

__device__ __forceinline__ void mma_pass(uint32_t aA0, uint32_t aA1,
                                         uint32_t bA0, uint32_t bA1,
                                         float acc[2][4][4]) {
    #pragma unroll
    for (int mi = 0; mi < 2; mi++)
        #pragma unroll
        for (int ni = 0; ni < 4; ni++)
            #pragma unroll
            for (int j = 0; j < 4; j++) acc[mi][ni][j] = 0.f;
    #pragma unroll
    for (int ks = 0; ks < 16; ks++) {
        uint32_t a0[4], a1[4], b01[4], b23[4];
        uint32_t ko = (uint32_t)ks * 32;
        ldsm4(a0,  aA0 + ko);
        ldsm4(a1,  aA1 + ko);
        ldsm4(b01, bA0 + ko);
        ldsm4(b23, bA1 + ko);
        mma_tf32(acc[0][0], a0, b01[0], b01[1]);
        mma_tf32(acc[0][1], a0, b01[2], b01[3]);
        mma_tf32(acc[0][2], a0, b23[0], b23[1]);
        mma_tf32(acc[0][3], a0, b23[2], b23[3]);
        mma_tf32(acc[1][0], a1, b01[0], b01[1]);
        mma_tf32(acc[1][1], a1, b01[2], b01[3]);
        mma_tf32(acc[1][2], a1, b23[0], b23[1]);
        mma_tf32(acc[1][3], a1, b23[2], b23[3]);
    }
}

__device__ __forceinline__ float sigm(float x) {
    return 1.f / (1.f + expf(-x));
}

// =====================================================================
// TF32 GEMM 64x64 tile, 256 threads, 3 CTAs/SM (occupancy-optimized):
// C[M,Ncols] = A[M,128] * B[128,Ncols] (+bias)(+relu)
// warp grid 2x4, warp tile 32x16, per k-step 3 LDSM.x4 + 4 MMA.
// =====================================================================
#define G64_SMEM_BYTES (2 * 64 * TS * 4)   // 67584 B

template<bool BIAS, bool RELU>
__global__ __launch_bounds__(256, 3)
void gemm64_tf32_kernel(const float* __restrict__ A,
                        const float* __restrict__ B,
                        const float* __restrict__ bias,
                        float* __restrict__ C,
                        int M, int Ncols) {
    extern __shared__ float smem[];
    float* As = smem;            // [64][TS]
    float* Bs = smem + 64 * TS;  // [64][TS]

    const int tid  = threadIdx.x;
    const int lane = tid & 31;
    const int wid  = tid >> 5;   // 0..7
    const int lr   = lane >> 2;
    const int lc   = lane & 3;
    const int bm = blockIdx.y * 64;
    const int bn = blockIdx.x * 64;

    // fill As[m][k]: 64 rows x 32 float4 = 2048 slots, 8 iters
    #pragma unroll
    for (int it = 0; it < 8; it++) {
        int i = it * 256 + tid;
        int m = i >> 5;
        int q = (i & 31) << 2;
        int gr = bm + m;
        float4 v = make_float4(0.f, 0.f, 0.f, 0.f);
        if (gr < M) v = *(const float4*)(A + (size_t)gr * 128 + q);
        *(float4*)(As + m * TS + q) = make_float4(to_tf32(v.x), to_tf32(v.y),
                                                  to_tf32(v.z), to_tf32(v.w));
    }
    // transpose fill Bs[n][k] = B[k][bn+n]: k 0..127, p 0..60 step 4
    #pragma unroll
    for (int it = 0; it < 8; it++) {
        int i = it * 256 + tid;
        int k = i >> 4;
        int p = (i & 15) << 2;
        float4 v = *(const float4*)(B + (size_t)k * Ncols + bn + p);
        Bs[(p + 0) * TS + k] = to_tf32(v.x);
        Bs[(p + 1) * TS + k] = to_tf32(v.y);
        Bs[(p + 2) * TS + k] = to_tf32(v.z);
        Bs[(p + 3) * TS + k] = to_tf32(v.w);
    }
    __syncthreads();

    const int wtm = wid & 1;     // 0..1
    const int wtn = wid >> 1;    // 0..3
    uint32_t as_base = (uint32_t)__cvta_generic_to_shared(As);
    uint32_t bs_base = (uint32_t)__cvta_generic_to_shared(Bs);
    int arow = (lane & 7) + ((lane >> 3) & 1) * 8;
    int acol = (lane >> 4) << 2;
    int brow = (lane & 7) + ((lane >> 4) << 3);
    int bcol = ((lane >> 3) & 1) << 2;
    uint32_t aA0 = as_base + (((wtm * 32 +  0 + arow) * TS + acol) << 2);
    uint32_t aA1 = as_base + (((wtm * 32 + 16 + arow) * TS + acol) << 2);
    uint32_t bA0 = bs_base + (((wtn * 16 + brow) * TS + bcol) << 2);

    float acc[2][2][4];
    #pragma unroll
    for (int mi = 0; mi < 2; mi++)
        #pragma unroll
        for (int ni = 0; ni < 2; ni++)
            #pragma unroll
            for (int j = 0; j < 4; j++) acc[mi][ni][j] = 0.f;

    #pragma unroll
    for (int ks = 0; ks < 16; ks++) {
        uint32_t a0[4], a1[4], b01[4];
        uint32_t ko = (uint32_t)ks * 32;
        ldsm4(a0,  aA0 + ko);
        ldsm4(a1,  aA1 + ko);
        ldsm4(b01, bA0 + ko);
        mma_tf32(acc[0][0], a0, b01[0], b01[1]);
        mma_tf32(acc[0][1], a0, b01[2], b01[3]);
        mma_tf32(acc[1][0], a1, b01[0], b01[1]);
        mma_tf32(acc[1][1], a1, b01[2], b01[3]);
    }

    #pragma unroll
    for (int mi = 0; mi < 2; mi++) {
        int r0 = bm + wtm * 32 + mi * 16 + lr;
        int r1 = r0 + 8;
        #pragma unroll
        for (int ni = 0; ni < 2; ni++) {
            int c0 = bn + wtn * 16 + ni * 8 + (lc << 1);
            float b0 = 0.f, b1 = 0.f;
            if (BIAS) { b0 = bias[c0]; b1 = bias[c0 + 1]; }
            float v0 = acc[mi][ni][0] + b0;
            float v1 = acc[mi][ni][1] + b1;
            float v2 = acc[mi][ni][2] + b0;
            float v3 = acc[mi][ni][3] + b1;
            if (RELU) {
                v0 = fmaxf(v0, 0.f); v1 = fmaxf(v1, 0.f);
                v2 = fmaxf(v2, 0.f); v3 = fmaxf(v3, 0.f);
            }
            if (r0 < M) *(float2*)(C + (size_t)r0 * Ncols + c0) = make_float2(v0, v1);
            if (r1 < M) *(float2*)(C + (size_t)r1 * Ncols + c0) = make_float2(v2, v3);
        }
    }
}

// =====================================================================
// FUSED GRU (measured-good from R12): h' = GRU(xh, h) in ONE kernel.
// =====================================================================
#define GRU_SMEM_BYTES (3 * 128 * TS * 4 + 2 * H3 * 4)   // 205824 B

__device__ __forceinline__ void load_w(float* Ws, const float* __restrict__ W,
                                       int tid) {
    #pragma unroll
    for (int it = 0; it < 8; it++) {
        int i = it * 512 + tid;
        int n = i >> 5;
        int q = (i & 31) << 2;
        float4 v = *(const float4*)(W + (size_t)n * 128 + q);
        *(float4*)(Ws + n * TS + q) = make_float4(to_tf32(v.x), to_tf32(v.y),
                                                  to_tf32(v.z), to_tf32(v.w));
    }
}

__global__ __launch_bounds__(512, 1)
void gru_fused_kernel(const float* __restrict__ xh,
                      const float* __restrict__ hin,
                      const float* __restrict__ Wih,
                      const float* __restrict__ Whh,
                      const float* __restrict__ bih,
                      const float* __restrict__ bhh,
                      float* __restrict__ hout,
                      int M) {
    extern __shared__ float smem[];
    float* Axh = smem;                 // [128][TS] tf32
    float* Ah  = smem + 128 * TS;      // [128][TS] raw fp32
    float* Ws  = smem + 256 * TS;      // [128][TS] weight slice
    float* bi_s = smem + 384 * TS;     // [384]
    float* bh_s = bi_s + H3;           // [384]

    const int tid  = threadIdx.x;
    const int lane = tid & 31;
    const int wid  = tid >> 5;
    const int lr   = lane >> 2;
    const int lc   = lane & 3;
    const int bm = blockIdx.x * 128;

    #pragma unroll
    for (int it = 0; it < 8; it++) {
        int i = it * 512 + tid;
        int m = i >> 5;
        int q = (i & 31) << 2;
        int gr = bm + m;
        float4 vx = make_float4(0.f, 0.f, 0.f, 0.f);
        float4 vh = make_float4(0.f, 0.f, 0.f, 0.f);
        if (gr < M) {
            vx = *(const float4*)(xh  + (size_t)gr * 128 + q);
            vh = *(const float4*)(hin + (size_t)gr * 128 + q);
        }
        *(float4*)(Axh + m * TS + q) = make_float4(to_tf32(vx.x), to_tf32(vx.y),
                                                   to_tf32(vx.z), to_tf32(vx.w));
        *(float4*)(Ah + m * TS + q) = vh;
    }
    if (tid < H3) { bi_s[tid] = bih[tid]; bh_s[tid] = bhh[tid]; }

    const int wtm = wid & 3;
    const int wtn = wid >> 2;
    int arow = (lane & 7) + ((lane >> 3) & 1) * 8;
    int acol = (lane >> 4) << 2;
    int brow = (lane & 7) + ((lane >> 4) << 3);
    int bcol = ((lane >> 3) & 1) << 2;
    uint32_t axh_b = (uint32_t)__cvta_generic_to_shared(Axh);
    uint32_t ah_b  = (uint32_t)__cvta_generic_to_shared(Ah);
    uint32_t ws_b  = (uint32_t)__cvta_generic_to_shared(Ws);
    uint32_t aO0 = ((wtm * 32 +  0 + arow) * TS + acol) << 2;
    uint32_t aO1 = ((wtm * 32 + 16 + arow) * TS + acol) << 2;
    uint32_t bO0 = ((wtn * 32 +  0 + brow) * TS + bcol) << 2;
    uint32_t bO1 = ((wtn * 32 + 16 + brow) * TS + bcol) << 2;

    float gi[2][4][4], gh[2][4][4], ra[2][4][4], na[2][4][4];

    // ======== gate r (slice 0) ========
    load_w(Ws, Wih, tid);
    __syncthreads();
    mma_pass(axh_b + aO0, axh_b + aO1, ws_b + bO0, ws_b + bO1, gi);
    __syncthreads();
    load_w(Ws, Whh, tid);
    __syncthreads();
    mma_pass(ah_b + aO0, ah_b + aO1, ws_b + bO0, ws_b + bO1, gh);
    #pragma unroll
    for (int mi = 0; mi < 2; mi++)
        #pragma unroll
        for (int ni = 0; ni < 4; ni++) {
            int col = wtn * 32 + ni * 8 + (lc << 1);
            float bs0 = bi_s[col] + bh_s[col];
            float bs1 = bi_s[col + 1] + bh_s[col + 1];
            ra[mi][ni][0] = sigm(gi[mi][ni][0] + gh[mi][ni][0] + bs0);
            ra[mi][ni][1] = sigm(gi[mi][ni][1] + gh[mi][ni][1] + bs1);
            ra[mi][ni][2] = sigm(gi[mi][ni][2] + gh[mi][ni][2] + bs0);
            ra[mi][ni][3] = sigm(gi[mi][ni][3] + gh[mi][ni][3] + bs1);
        }

    // ======== gate n (slice 2) ========
    __syncthreads();
    load_w(Ws, Wih + 2 * 128 * 128, tid);
    __syncthreads();
    mma_pass(axh_b + aO0, axh_b + aO1, ws_b + bO0, ws_b + bO1, gi);
    __syncthreads();
    load_w(Ws, Whh + 2 * 128 * 128, tid);
    __syncthreads();
    mma_pass(ah_b + aO0, ah_b + aO1, ws_b + bO0, ws_b + bO1, gh);
    #pragma unroll
    for (int mi = 0; mi < 2; mi++)
        #pragma unroll
        for (int ni = 0; ni < 4; ni++) {
            int col = wtn * 32 + ni * 8 + (lc << 1);
            float bi0 = bi_s[256 + col], bi1 = bi_s[256 + col + 1];
            float bh0 = bh_s[256 + col], bh1 = bh_s[256 + col + 1];
            na[mi][ni][0] = tanhf(gi[mi][ni][0] + bi0 + ra[mi][ni][0] * (gh[mi][ni][0] + bh0));
            na[mi][ni][1] = tanhf(gi[mi][ni][1] + bi1 + ra[mi][ni][1] * (gh[mi][ni][1] + bh1));
            na[mi][ni][2] = tanhf(gi[mi][ni][2] + bi0 + ra[mi][ni][2] * (gh[mi][ni][2] + bh0));
            na[mi][ni][3] = tanhf(gi[mi][ni][3] + bi1 + ra[mi][ni][3] * (gh[mi][ni][3] + bh1));
        }

    // ======== gate z (slice 1) + blend + store ========
    __syncthreads();
    load_w(Ws, Wih + 128 * 128, tid);
    __syncthreads();
    mma_pass(axh_b + aO0, axh_b + aO1, ws_b + bO0, ws_b + bO1, gi);
    __syncthreads();
    load_w(Ws, Whh + 128 * 128, tid);
    __syncthreads();
    mma_pass(ah_b + aO0, ah_b + aO1, ws_b + bO0, ws_b + bO1, gh);
    #pragma unroll
    for (int mi = 0; mi < 2; mi++) {
        int row0 = wtm * 32 + mi * 16 + lr;
        int row1 = row0 + 8;
        int gr0 = bm + row0, gr1 = bm + row1;
        #pragma unroll
        for (int ni = 0; ni < 4; ni++) {
            int col = wtn * 32 + ni * 8 + (lc << 1);
            float bs0 = bi_s[128 + col] + bh_s[128 + col];
            float bs1 = bi_s[128 + col + 1] + bh_s[128 + col + 1];
            float z0 = sigm(gi[mi][ni][0] + gh[mi][ni][0] + bs0);
            float z1 = sigm(gi[mi][ni][1] + gh[mi][ni][1] + bs1);
            float z2 = sigm(gi[mi][ni][2] + gh[mi][ni][2] + bs0);
            float z3 = sigm(gi[mi][ni][3] + gh[mi][ni][3] + bs1);
            float2 h0v = *(float2*)(Ah + row0 * TS + col);
            float2 h1v = *(float2*)(Ah + row1 * TS + col);
            float v0 = (1.f - z0) * na[mi][ni][0] + z0 * h0v.x;
            float v1 = (1.f - z1) * na[mi][ni][1] + z1 * h0v.y;
            float v2 = (1.f - z2) * na[mi][ni][2] + z2 * h1v.x;
            float v3 = (1.f - z3) * na[mi][ni][3] + z3 * h1v.y;
            if (gr0 < M) *(float2*)(hout + (size_t)gr0 * 128 + col) = make_float2(v0, v1);
            if (gr1 < M) *(float2*)(hout + (size_t)gr1 * 128 + col) = make_float2(v2, v3);
        }
    }
}

// ---------------- fp32 fallback GEMM (fc, Ncols=40) ----------------------
__global__ void gemm_fc_kernel(const float* __restrict__ A,
                               const float* __restrict__ B,
                               const float* __restrict__ bias,
                               float* __restrict__ C,
                               int M, int Ncols) {
    constexpr int K  = 128;
    constexpr int BM = 64, BN = 64, BK = 16;
    __shared__ float As[BK][BM + 4];
    __shared__ float Bs[BK][BN + 4];

    const int tid = threadIdx.x;
    const int bm = blockIdx.y * BM;
    const int bn = blockIdx.x * BN;
    const int tx = tid & 15;
    const int ty = tid >> 4;

    float acc[4][4] = {};

    for (int k0 = 0; k0 < K; k0 += BK) {
        {
            const int arow = tid >> 2;
            const int acol = (tid & 3) << 2;
            float4 av = make_float4(0.f, 0.f, 0.f, 0.f);
            const int gr = bm + arow;
            if (gr < M)
                av = *(const float4*)(A + (size_t)gr * K + k0 + acol);
            As[acol + 0][arow] = av.x;
            As[acol + 1][arow] = av.y;
            As[acol + 2][arow] = av.z;
            As[acol + 3][arow] = av.w;
        }
        {
            const int brow = tid >> 4;
            const int bcol = (tid & 15) << 2;
            const int gc = bn + bcol;
            Bs[brow][bcol + 0] = (gc + 0 < Ncols) ? B[(size_t)(k0 + brow) * Ncols + gc + 0] : 0.f;
            Bs[brow][bcol + 1] = (gc + 1 < Ncols) ? B[(size_t)(k0 + brow) * Ncols + gc + 1] : 0.f;
            Bs[brow][bcol + 2] = (gc + 2 < Ncols) ? B[(size_t)(k0 + brow) * Ncols + gc + 2] : 0.f;
            Bs[brow][bcol + 3] = (gc + 3 < Ncols) ? B[(size_t)(k0 + brow) * Ncols + gc + 3] : 0.f;
        }
        __syncthreads();

        #pragma unroll
        for (int k = 0; k < BK; k++) {
            float4 a = *(const float4*)(&As[k][ty << 2]);
            float4 b = *(const float4*)(&Bs[k][tx << 2]);
            acc[0][0] += a.x * b.x; acc[0][1] += a.x * b.y;
            acc[0][2] += a.x * b.z; acc[0][3] += a.x * b.w;
            acc[1][0] += a.y * b.x; acc[1][1] += a.y * b.y;
            acc[1][2] += a.y * b.z; acc[1][3] += a.y * b.w;
            acc[2][0] += a.z * b.x; acc[2][1] += a.z * b.y;
            acc[2][2] += a.z * b.z; acc[2][3] += a.z * b.w;
            acc[3][0] += a.w * b.x; acc[3][1] += a.w * b.y;
            acc[3][2] += a.w * b.z; acc[3][3] += a.w * b.w;
        }
        __syncthreads();
    }

    float bv[4] = {0.f, 0.f, 0.f, 0.f};
    #pragma unroll
    for (int j = 0; j < 4; j++) {
        int c = bn + (tx << 2) + j;
        bv[j] = (c < Ncols) ? bias[c] : 0.f;
    }
    #pragma unroll
    for (int i = 0; i < 4; i++) {
        int r = bm + (ty << 2) + i;
        if (r >= M) continue;
        #pragma unroll
        for (int j = 0; j < 4; j++) {
            int c = bn + (tx << 2) + j;
            if (c >= Ncols) continue;
            C[(size_t)r * Ncols + c] = acc[i][j] + bv[j];
        }
    }
}

// ---------------- host orchestration ----------------
extern "C" void kernel_launch(void* const* d_in, const int* in_sizes, int n_in,
                              void* d_out, int out_size) {
    const float* x     = (const float*)d_in[0];
    const int*   ei    = (const int*)  d_in[1];
    const float* ew    = (const float*)d_in[2];
    const float* h0    = (const float*)d_in[3];
    const float* linW  = (const float*)d_in[4];
    const float* linB  = (const float*)d_in[5];
    const float* convW = (const float*)d_in[6];
    const float* convB = (const float*)d_in[7];
    const float* Wih   = (const float*)d_in[8];
    const float* Whh   = (const float*)d_in[9];
    const float* bih   = (const float*)d_in[10];
    const float* bhh   = (const float*)d_in[11];
    const float* fcW   = (const float*)d_in[12];
    const float* fcB   = (const float*)d_in[13];
    float* out = (float*)d_out;

    const int* src = ei;
    const int* dst = ei + EE;

    static bool s_attr_done = false;
    if (!s_attr_done) {
        cudaFuncSetAttribute(gemm64_tf32_kernel<true, true>,
                             cudaFuncAttributeMaxDynamicSharedMemorySize, G64_SMEM_BYTES);
        cudaFuncSetAttribute(gemm64_tf32_kernel<false, false>,
                             cudaFuncAttributeMaxDynamicSharedMemorySize, G64_SMEM_BYTES);
        cudaFuncSetAttribute(gru_fused_kernel,
                             cudaFuncAttributeMaxDynamicSharedMemorySize, GRU_SMEM_BYTES);
        s_attr_done = true;
    }

    float *p_xh, *p_xw, *p_h;
    cudaGetSymbolAddress((void**)&p_xh, g_xh);
    cudaGetSymbolAddress((void**)&p_xw, g_xw);
    cudaGetSymbolAddress((void**)&p_h,  g_h);

    const int EB = 256;
    const int NB = (NN + 127) / 128;       // 782  (GRU CTAs)
    const int NB64 = (NN + 63) / 64;       // 1563 (GEMM CTAs rows)

    const dim3 blk256(256);
    const dim3 blk512(512);
    const dim3 g64_128(2, NB64);           // Ncols=128

    // ---- degree + histogram + CSR build (once, reused 3x) ----
    init_deg_kernel<<<(NN + 255) / 256, 256>>>();
    accum_deg_kernel<<<(EE + EB - 1) / EB, EB>>>(dst, ew);
    dinv_kernel<<<(NN + 255) / 256, 256>>>();
    scan1_kernel<<<NBLK, SCAN_B>>>();
    scan2_kernel<<<1, 256>>>();
    scan3_kernel<<<(NN + 255) / 256, 256>>>();
    fill_kernel<<<(EE + EB - 1) / EB, EB>>>(src, dst, ew);

    // xh = relu(x @ linW + linB)
    gemm64_tf32_kernel<true, true><<<g64_128, blk256, G64_SMEM_BYTES>>>(
        x, linW, linB, p_xh, NN, FH);

    // h = GRU(xh, h0)
    gru_fused_kernel<<<NB, blk512, GRU_SMEM_BYTES>>>(
        p_xh, h0, Wih, Whh, bih, bhh, p_h, NN);

    for (int l = 0; l < LL; l++) {
        const float* W = convW + (size_t)l * FH * FH;
        const float* b = convB + (size_t)l * FH;
        // xw = xh @ W
        gemm64_tf32_kernel<false, false><<<g64_128, blk256, G64_SMEM_BYTES>>>(
            p_xh, W, nullptr, p_xw, NN, FH);
        // xh = relu(selfloop + gather-agg + bias)   [no atomics]
        gather_agg_kernel<<<(NN * 32 + 255) / 256, 256>>>(p_xw, b, p_xh);
        // h = GRU(xh, h)
        gru_fused_kernel<<<NB, blk512, GRU_SMEM_BYTES>>>(
            p_xh, p_h, Wih, Whh, bih, bhh, p_h, NN);
    }

    // out = h @ fcW + fcB
    {
        dim3 grid((CC + 63) / 64, (NN + 63) / 64);
        gemm_fc_kernel<<<grid, 256>>>(p_h, fcW, fcB, out, NN, CC);
    }
}

// round 15
// speedup vs baseline: 3.2598x; 1.0733x over previous
#include <cuda_runtime.h>
#include <cstdint>

// Problem constants (fixed by reference)
#define NN   100000
#define EE   1600000
#define FH   128      // F_IN == H == HG
#define H3   384      // 3*HG
#define CC   40
#define LL   3

// ---------------- scratch (device globals; no allocation allowed) ----------
__device__ float g_xh1[(size_t)NN * FH];
__device__ float g_xh2[(size_t)NN * FH];
__device__ float g_xw[(size_t)NN * FH];
__device__ float g_h [(size_t)NN * FH];
__device__ float g_deg [NN];
__device__ float g_dinv[NN];
// CSR (dst-sorted edge list, rebuilt every call)
__device__ int   g_cnt[NN];          // histogram, then cursor
__device__ int   g_rowstart[NN + 1];
__device__ int   g_blocksum[256];
__device__ int   g_esrc[EE];
__device__ float g_ew2[EE];

#define SCAN_B 512
#define NBLK ((NN + SCAN_B - 1) / SCAN_B)   // 196

// ---------------- degree + histogram ----------------
__global__ void init_deg_kernel() {
    int i = blockIdx.x * blockDim.x + threadIdx.x;
    if (i < NN) { g_deg[i] = 1.0f; g_cnt[i] = 0; }   // self-loop weight 1
}

__global__ void accum_deg_kernel(const int* __restrict__ dst,
                                 const float* __restrict__ ew) {
    int e = blockIdx.x * blockDim.x + threadIdx.x;
    if (e < EE) {
        int d = dst[e];
        atomicAdd(&g_deg[d], ew[e]);
        atomicAdd(&g_cnt[d], 1);
    }
}

__global__ void dinv_kernel() {
    int i = blockIdx.x * blockDim.x + threadIdx.x;
    if (i < NN) g_dinv[i] = rsqrtf(g_deg[i]);   // deg >= 1 always
}

// ---------------- exclusive scan over g_cnt -> g_rowstart ----------------
__global__ void scan1_kernel() {
    __shared__ int sh[SCAN_B];
    int b = blockIdx.x, t = threadIdx.x;
    int i = b * SCAN_B + t;
    int v = (i < NN) ? g_cnt[i] : 0;
    sh[t] = v;
    __syncthreads();
    #pragma unroll
    for (int off = 1; off < SCAN_B; off <<= 1) {
        int x = (t >= off) ? sh[t - off] : 0;
        __syncthreads();
        sh[t] += x;
        __syncthreads();
    }
    if (i < NN) g_rowstart[i] = sh[t] - v;            // block-local exclusive
    if (t == SCAN_B - 1) g_blocksum[b] = sh[t];       // block total
}

__global__ void scan2_kernel() {
    __shared__ int sh[256];
    int t = threadIdx.x;   // 256 threads, NBLK=196
    int v = (t < NBLK) ? g_blocksum[t] : 0;
    sh[t] = v;
    __syncthreads();
    #pragma unroll
    for (int off = 1; off < 256; off <<= 1) {
        int x = (t >= off) ? sh[t - off] : 0;
        __syncthreads();
        sh[t] += x;
        __syncthreads();
    }
    if (t < NBLK) g_blocksum[t] = sh[t] - v;          // exclusive
}

__global__ void scan3_kernel() {
    int i = blockIdx.x * blockDim.x + threadIdx.x;
    if (i < NN) {
        int v = g_rowstart[i] + g_blocksum[i / SCAN_B];
        g_rowstart[i] = v;
        g_cnt[i] = v;      // cursor for fill
    }
    if (i == 0) g_rowstart[NN] = EE;
}

// ---------------- fill CSR: src + precomputed norm ----------------
__global__ void fill_kernel(const int* __restrict__ src,
                            const int* __restrict__ dst,
                            const float* __restrict__ ew) {
    int e = blockIdx.x * blockDim.x + threadIdx.x;
    if (e >= EE) return;
    int s = src[e], d = dst[e];
    int pos = atomicAdd(&g_cnt[d], 1);
    g_esrc[pos] = s;
    g_ew2[pos] = g_dinv[s] * ew[e] * g_dinv[d];
}

// ---------------- gather aggregation: warp per dst node, NO atomics ------
__global__ void gather_agg_kernel(const float* __restrict__ xw,
                                  const float* __restrict__ bias,
                                  float* __restrict__ xh) {
    int d = (blockIdx.x * blockDim.x + threadIdx.x) >> 5;
    int lane = threadIdx.x & 31;
    if (d >= NN) return;
    float di = g_dinv[d];
    float sw = di * di;
    float4 acc = ((const float4*)(xw + (size_t)d * FH))[lane];
    acc.x *= sw; acc.y *= sw; acc.z *= sw; acc.w *= sw;
    int beg = g_rowstart[d], end = g_rowstart[d + 1];
    int i = beg;
    for (; i + 3 < end; i += 4) {                 // MLP=4
        int s0 = g_esrc[i], s1 = g_esrc[i + 1];
        int s2 = g_esrc[i + 2], s3 = g_esrc[i + 3];
        float w0 = g_ew2[i], w1 = g_ew2[i + 1];
        float w2 = g_ew2[i + 2], w3 = g_ew2[i + 3];
        float4 v0 = ((const float4*)(xw + (size_t)s0 * FH))[lane];
        float4 v1 = ((const float4*)(xw + (size_t)s1 * FH))[lane];
        float4 v2 = ((const float4*)(xw + (size_t)s2 * FH))[lane];
        float4 v3 = ((const float4*)(xw + (size_t)s3 * FH))[lane];
        acc.x += v0.x * w0 + v1.x * w1 + v2.x * w2 + v3.x * w3;
        acc.y += v0.y * w0 + v1.y * w1 + v2.y * w2 + v3.y * w3;
        acc.z += v0.z * w0 + v1.z * w1 + v2.z * w2 + v3.z * w3;
        acc.w += v0.w * w0 + v1.w * w1 + v2.w * w2 + v3.w * w3;
    }
    for (; i < end; i++) {
        int s = g_esrc[i];
        float w = g_ew2[i];
        float4 v = ((const float4*)(xw + (size_t)s * FH))[lane];
        acc.x += v.x * w; acc.y += v.y * w;
        acc.z += v.z * w; acc.w += v.w * w;
    }
    float4 b = ((const float4*)bias)[lane];
    acc.x = fmaxf(acc.x + b.x, 0.f);
    acc.y = fmaxf(acc.y + b.y, 0.f);
    acc.z = fmaxf(acc.z + b.z, 0.f);
    acc.w = fmaxf(acc.w + b.w, 0.f);
    ((float4*)(xh + (size_t)d * FH))[lane] = acc;
}

// ---------------- shared MMA machinery (measured-good from R8) ------------
#define TS 132

__device__ __forceinline__ float to_tf32(float v) {
    uint32_t o;
    asm volatile("cvt.rna.tf32.f32 %0, %1;" : "=r"(o) : "f"(v));
    return __uint_as_float(o);
}

__device__ __forceinline__ void ldsm4(uint32_t* r, uint32_t addr) {
    asm volatile(
        "ldmatrix.sync.aligned.m8n8.x4.shared.b16 {%0,%1,%2,%3}, [%4];"
        : "=r"(r[0]), "=r"(r[1]), "=r"(r[2]), "=r"(r[3]) : "r"(addr));
}

__device__ __forceinline__ void mma_tf32(float* d, const uint32_t* a,
                                         uint32_t b0, uint32_t b1) {
    asm volatile(
        "mma.sync.aligned.m16n8k8.row.col.f32.tf32.tf32.f32 "
        "{%0,%1,%2,%3}, {%4,%5,%6,%7}, {%8,%9}, {%0,%1,%2,%3};\n"
        : "+f"(d[0]), "+f"(d[1]), "+f"(d[2]), "+f"(d[3])
        : "r"(a[0]), "r"(a[1]), "r"(a[2]), "r"(a[3]), "r"(b0), "r"(b1));
}

__device__ __forceinline__ void mma_pass(uint32_t aA0, uint32_t aA1,
                                         uint32_t bA0, uint32_t bA1,
                                         float acc[2][4][4]) {
    #pragma unroll
    for (int mi = 0; mi < 2; mi++)
        #pragma unroll
        for (int ni = 0; ni < 4; ni++)
            #pragma unroll
            for (int j = 0; j < 4; j++) acc[mi][ni][j] = 0.f;
    #pragma unroll
    for (int ks = 0; ks < 16; ks++) {
        uint32_t a0[4], a1[4], b01[4], b23[4];
        uint32_t ko = (uint32_t)ks * 32;
        ldsm4(a0,  aA0 + ko);
        ldsm4(a1,  aA1 + ko);
        ldsm4(b01, bA0 + ko);
        ldsm4(b23, bA1 + ko);
        mma_tf32(acc[0][0], a0, b01[0], b01[1]);
        mma_tf32(acc[0][1], a0, b01[2], b01[3]);
        mma_tf32(acc[0][2], a0, b23[0], b23[1]);
        mma_tf32(acc[0][3], a0, b23[2], b23[3]);
        mma_tf32(acc[1][0], a1, b01[0], b01[1]);
        mma_tf32(acc[1][1], a1, b01[2], b01[3]);
        mma_tf32(acc[1][2], a1, b23[0], b23[1]);
        mma_tf32(acc[1][3], a1, b23[2], b23[3]);
    }
}

__device__ __forceinline__ float sigm(float x) {
    return 1.f / (1.f + expf(-x));
}

// =====================================================================
// TF32 GEMM 64x64 tile, 256 threads, 3 CTAs/SM (measured-good from R14)
// =====================================================================
#define G64_SMEM_BYTES (2 * 64 * TS * 4)   // 67584 B

template<bool BIAS, bool RELU>
__global__ __launch_bounds__(256, 3)
void gemm64_tf32_kernel(const float* __restrict__ A,
                        const float* __restrict__ B,
                        const float* __restrict__ bias,
                        float* __restrict__ C,
                        int M, int Ncols) {
    extern __shared__ float smem[];
    float* As = smem;            // [64][TS]
    float* Bs = smem + 64 * TS;  // [64][TS]

    const int tid  = threadIdx.x;
    const int lane = tid & 31;
    const int wid  = tid >> 5;   // 0..7
    const int lr   = lane >> 2;
    const int lc   = lane & 3;
    const int bm = blockIdx.y * 64;
    const int bn = blockIdx.x * 64;

    #pragma unroll
    for (int it = 0; it < 8; it++) {
        int i = it * 256 + tid;
        int m = i >> 5;
        int q = (i & 31) << 2;
        int gr = bm + m;
        float4 v = make_float4(0.f, 0.f, 0.f, 0.f);
        if (gr < M) v = *(const float4*)(A + (size_t)gr * 128 + q);
        *(float4*)(As + m * TS + q) = make_float4(to_tf32(v.x), to_tf32(v.y),
                                                  to_tf32(v.z), to_tf32(v.w));
    }
    #pragma unroll
    for (int it = 0; it < 8; it++) {
        int i = it * 256 + tid;
        int k = i >> 4;
        int p = (i & 15) << 2;
        float4 v = *(const float4*)(B + (size_t)k * Ncols + bn + p);
        Bs[(p + 0) * TS + k] = to_tf32(v.x);
        Bs[(p + 1) * TS + k] = to_tf32(v.y);
        Bs[(p + 2) * TS + k] = to_tf32(v.z);
        Bs[(p + 3) * TS + k] = to_tf32(v.w);
    }
    __syncthreads();

    const int wtm = wid & 1;
    const int wtn = wid >> 1;
    uint32_t as_base = (uint32_t)__cvta_generic_to_shared(As);
    uint32_t bs_base = (uint32_t)__cvta_generic_to_shared(Bs);
    int arow = (lane & 7) + ((lane >> 3) & 1) * 8;
    int acol = (lane >> 4) << 2;
    int brow = (lane & 7) + ((lane >> 4) << 3);
    int bcol = ((lane >> 3) & 1) << 2;
    uint32_t aA0 = as_base + (((wtm * 32 +  0 + arow) * TS + acol) << 2);
    uint32_t aA1 = as_base + (((wtm * 32 + 16 + arow) * TS + acol) << 2);
    uint32_t bA0 = bs_base + (((wtn * 16 + brow) * TS + bcol) << 2);

    float acc[2][2][4];
    #pragma unroll
    for (int mi = 0; mi < 2; mi++)
        #pragma unroll
        for (int ni = 0; ni < 2; ni++)
            #pragma unroll
            for (int j = 0; j < 4; j++) acc[mi][ni][j] = 0.f;

    #pragma unroll
    for (int ks = 0; ks < 16; ks++) {
        uint32_t a0[4], a1[4], b01[4];
        uint32_t ko = (uint32_t)ks * 32;
        ldsm4(a0,  aA0 + ko);
        ldsm4(a1,  aA1 + ko);
        ldsm4(b01, bA0 + ko);
        mma_tf32(acc[0][0], a0, b01[0], b01[1]);
        mma_tf32(acc[0][1], a0, b01[2], b01[3]);
        mma_tf32(acc[1][0], a1, b01[0], b01[1]);
        mma_tf32(acc[1][1], a1, b01[2], b01[3]);
    }

    #pragma unroll
    for (int mi = 0; mi < 2; mi++) {
        int r0 = bm + wtm * 32 + mi * 16 + lr;
        int r1 = r0 + 8;
        #pragma unroll
        for (int ni = 0; ni < 2; ni++) {
            int c0 = bn + wtn * 16 + ni * 8 + (lc << 1);
            float b0 = 0.f, b1 = 0.f;
            if (BIAS) { b0 = bias[c0]; b1 = bias[c0 + 1]; }
            float v0 = acc[mi][ni][0] + b0;
            float v1 = acc[mi][ni][1] + b1;
            float v2 = acc[mi][ni][2] + b0;
            float v3 = acc[mi][ni][3] + b1;
            if (RELU) {
                v0 = fmaxf(v0, 0.f); v1 = fmaxf(v1, 0.f);
                v2 = fmaxf(v2, 0.f); v3 = fmaxf(v3, 0.f);
            }
            if (r0 < M) *(float2*)(C + (size_t)r0 * Ncols + c0) = make_float2(v0, v1);
            if (r1 < M) *(float2*)(C + (size_t)r1 * Ncols + c0) = make_float2(v2, v3);
        }
    }
}

// =====================================================================
// FUSED GRU (measured-good from R12)
// =====================================================================
#define GRU_SMEM_BYTES (3 * 128 * TS * 4 + 2 * H3 * 4)   // 205824 B

__device__ __forceinline__ void load_w(float* Ws, const float* __restrict__ W,
                                       int tid) {
    #pragma unroll
    for (int it = 0; it < 8; it++) {
        int i = it * 512 + tid;
        int n = i >> 5;
        int q = (i & 31) << 2;
        float4 v = *(const float4*)(W + (size_t)n * 128 + q);
        *(float4*)(Ws + n * TS + q) = make_float4(to_tf32(v.x), to_tf32(v.y),
                                                  to_tf32(v.z), to_tf32(v.w));
    }
}

__global__ __launch_bounds__(512, 1)
void gru_fused_kernel(const float* __restrict__ xh,
                      const float* __restrict__ hin,
                      const float* __restrict__ Wih,
                      const float* __restrict__ Whh,
                      const float* __restrict__ bih,
                      const float* __restrict__ bhh,
                      float* __restrict__ hout,
                      int M) {
    extern __shared__ float smem[];
    float* Axh = smem;
    float* Ah  = smem + 128 * TS;
    float* Ws  = smem + 256 * TS;
    float* bi_s = smem + 384 * TS;
    float* bh_s = bi_s + H3;

    const int tid  = threadIdx.x;
    const int lane = tid & 31;
    const int wid  = tid >> 5;
    const int lr   = lane >> 2;
    const int lc   = lane & 3;
    const int bm = blockIdx.x * 128;

    #pragma unroll
    for (int it = 0; it < 8; it++) {
        int i = it * 512 + tid;
        int m = i >> 5;
        int q = (i & 31) << 2;
        int gr = bm + m;
        float4 vx = make_float4(0.f, 0.f, 0.f, 0.f);
        float4 vh = make_float4(0.f, 0.f, 0.f, 0.f);
        if (gr < M) {
            vx = *(const float4*)(xh  + (size_t)gr * 128 + q);
            vh = *(const float4*)(hin + (size_t)gr * 128 + q);
        }
        *(float4*)(Axh + m * TS + q) = make_float4(to_tf32(vx.x), to_tf32(vx.y),
                                                   to_tf32(vx.z), to_tf32(vx.w));
        *(float4*)(Ah + m * TS + q) = vh;
    }
    if (tid < H3) { bi_s[tid] = bih[tid]; bh_s[tid] = bhh[tid]; }

    const int wtm = wid & 3;
    const int wtn = wid >> 2;
    int arow = (lane & 7) + ((lane >> 3) & 1) * 8;
    int acol = (lane >> 4) << 2;
    int brow = (lane & 7) + ((lane >> 4) << 3);
    int bcol = ((lane >> 3) & 1) << 2;
    uint32_t axh_b = (uint32_t)__cvta_generic_to_shared(Axh);
    uint32_t ah_b  = (uint32_t)__cvta_generic_to_shared(Ah);
    uint32_t ws_b  = (uint32_t)__cvta_generic_to_shared(Ws);
    uint32_t aO0 = ((wtm * 32 +  0 + arow) * TS + acol) << 2;
    uint32_t aO1 = ((wtm * 32 + 16 + arow) * TS + acol) << 2;
    uint32_t bO0 = ((wtn * 32 +  0 + brow) * TS + bcol) << 2;
    uint32_t bO1 = ((wtn * 32 + 16 + brow) * TS + bcol) << 2;

    float gi[2][4][4], gh[2][4][4], ra[2][4][4], na[2][4][4];

    // ======== gate r (slice 0) ========
    load_w(Ws, Wih, tid);
    __syncthreads();
    mma_pass(axh_b + aO0, axh_b + aO1, ws_b + bO0, ws_b + bO1, gi);
    __syncthreads();
    load_w(Ws, Whh, tid);
    __syncthreads();
    mma_pass(ah_b + aO0, ah_b + aO1, ws_b + bO0, ws_b + bO1, gh);
    #pragma unroll
    for (int mi = 0; mi < 2; mi++)
        #pragma unroll
        for (int ni = 0; ni < 4; ni++) {
            int col = wtn * 32 + ni * 8 + (lc << 1);
            float bs0 = bi_s[col] + bh_s[col];
            float bs1 = bi_s[col + 1] + bh_s[col + 1];
            ra[mi][ni][0] = sigm(gi[mi][ni][0] + gh[mi][ni][0] + bs0);
            ra[mi][ni][1] = sigm(gi[mi][ni][1] + gh[mi][ni][1] + bs1);
            ra[mi][ni][2] = sigm(gi[mi][ni][2] + gh[mi][ni][2] + bs0);
            ra[mi][ni][3] = sigm(gi[mi][ni][3] + gh[mi][ni][3] + bs1);
        }

    // ======== gate n (slice 2) ========
    __syncthreads();
    load_w(Ws, Wih + 2 * 128 * 128, tid);
    __syncthreads();
    mma_pass(axh_b + aO0, axh_b + aO1, ws_b + bO0, ws_b + bO1, gi);
    __syncthreads();
    load_w(Ws, Whh + 2 * 128 * 128, tid);
    __syncthreads();
    mma_pass(ah_b + aO0, ah_b + aO1, ws_b + bO0, ws_b + bO1, gh);
    #pragma unroll
    for (int mi = 0; mi < 2; mi++)
        #pragma unroll
        for (int ni = 0; ni < 4; ni++) {
            int col = wtn * 32 + ni * 8 + (lc << 1);
            float bi0 = bi_s[256 + col], bi1 = bi_s[256 + col + 1];
            float bh0 = bh_s[256 + col], bh1 = bh_s[256 + col + 1];
            na[mi][ni][0] = tanhf(gi[mi][ni][0] + bi0 + ra[mi][ni][0] * (gh[mi][ni][0] + bh0));
            na[mi][ni][1] = tanhf(gi[mi][ni][1] + bi1 + ra[mi][ni][1] * (gh[mi][ni][1] + bh1));
            na[mi][ni][2] = tanhf(gi[mi][ni][2] + bi0 + ra[mi][ni][2] * (gh[mi][ni][2] + bh0));
            na[mi][ni][3] = tanhf(gi[mi][ni][3] + bi1 + ra[mi][ni][3] * (gh[mi][ni][3] + bh1));
        }

    // ======== gate z (slice 1) + blend + store ========
    __syncthreads();
    load_w(Ws, Wih + 128 * 128, tid);
    __syncthreads();
    mma_pass(axh_b + aO0, axh_b + aO1, ws_b + bO0, ws_b + bO1, gi);
    __syncthreads();
    load_w(Ws, Whh + 128 * 128, tid);
    __syncthreads();
    mma_pass(ah_b + aO0, ah_b + aO1, ws_b + bO0, ws_b + bO1, gh);
    #pragma unroll
    for (int mi = 0; mi < 2; mi++) {
        int row0 = wtm * 32 + mi * 16 + lr;
        int row1 = row0 + 8;
        int gr0 = bm + row0, gr1 = bm + row1;
        #pragma unroll
        for (int ni = 0; ni < 4; ni++) {
            int col = wtn * 32 + ni * 8 + (lc << 1);
            float bs0 = bi_s[128 + col] + bh_s[128 + col];
            float bs1 = bi_s[128 + col + 1] + bh_s[128 + col + 1];
            float z0 = sigm(gi[mi][ni][0] + gh[mi][ni][0] + bs0);
            float z1 = sigm(gi[mi][ni][1] + gh[mi][ni][1] + bs1);
            float z2 = sigm(gi[mi][ni][2] + gh[mi][ni][2] + bs0);
            float z3 = sigm(gi[mi][ni][3] + gh[mi][ni][3] + bs1);
            float2 h0v = *(float2*)(Ah + row0 * TS + col);
            float2 h1v = *(float2*)(Ah + row1 * TS + col);
            float v0 = (1.f - z0) * na[mi][ni][0] + z0 * h0v.x;
            float v1 = (1.f - z1) * na[mi][ni][1] + z1 * h0v.y;
            float v2 = (1.f - z2) * na[mi][ni][2] + z2 * h1v.x;
            float v3 = (1.f - z3) * na[mi][ni][3] + z3 * h1v.y;
            if (gr0 < M) *(float2*)(hout + (size_t)gr0 * 128 + col) = make_float2(v0, v1);
            if (gr1 < M) *(float2*)(hout + (size_t)gr1 * 128 + col) = make_float2(v2, v3);
        }
    }
}

// ---------------- fp32 fallback GEMM (fc, Ncols=40) ----------------------
__global__ void gemm_fc_kernel(const float* __restrict__ A,
                               const float* __restrict__ B,
                               const float* __restrict__ bias,
                               float* __restrict__ C,
                               int M, int Ncols) {
    constexpr int K  = 128;
    constexpr int BM = 64, BN = 64, BK = 16;
    __shared__ float As[BK][BM + 4];
    __shared__ float Bs[BK][BN + 4];

    const int tid = threadIdx.x;
    const int bm = blockIdx.y * BM;
    const int bn = blockIdx.x * BN;
    const int tx = tid & 15;
    const int ty = tid >> 4;

    float acc[4][4] = {};

    for (int k0 = 0; k0 < K; k0 += BK) {
        {
            const int arow = tid >> 2;
            const int acol = (tid & 3) << 2;
            float4 av = make_float4(0.f, 0.f, 0.f, 0.f);
            const int gr = bm + arow;
            if (gr < M)
                av = *(const float4*)(A + (size_t)gr * K + k0 + acol);
            As[acol + 0][arow] = av.x;
            As[acol + 1][arow] = av.y;
            As[acol + 2][arow] = av.z;
            As[acol + 3][arow] = av.w;
        }
        {
            const int brow = tid >> 4;
            const int bcol = (tid & 15) << 2;
            const int gc = bn + bcol;
            Bs[brow][bcol + 0] = (gc + 0 < Ncols) ? B[(size_t)(k0 + brow) * Ncols + gc + 0] : 0.f;
            Bs[brow][bcol + 1] = (gc + 1 < Ncols) ? B[(size_t)(k0 + brow) * Ncols + gc + 1] : 0.f;
            Bs[brow][bcol + 2] = (gc + 2 < Ncols) ? B[(size_t)(k0 + brow) * Ncols + gc + 2] : 0.f;
            Bs[brow][bcol + 3] = (gc + 3 < Ncols) ? B[(size_t)(k0 + brow) * Ncols + gc + 3] : 0.f;
        }
        __syncthreads();

        #pragma unroll
        for (int k = 0; k < BK; k++) {
            float4 a = *(const float4*)(&As[k][ty << 2]);
            float4 b = *(const float4*)(&Bs[k][tx << 2]);
            acc[0][0] += a.x * b.x; acc[0][1] += a.x * b.y;
            acc[0][2] += a.x * b.z; acc[0][3] += a.x * b.w;
            acc[1][0] += a.y * b.x; acc[1][1] += a.y * b.y;
            acc[1][2] += a.y * b.z; acc[1][3] += a.y * b.w;
            acc[2][0] += a.z * b.x; acc[2][1] += a.z * b.y;
            acc[2][2] += a.z * b.z; acc[2][3] += a.z * b.w;
            acc[3][0] += a.w * b.x; acc[3][1] += a.w * b.y;
            acc[3][2] += a.w * b.z; acc[3][3] += a.w * b.w;
        }
        __syncthreads();
    }

    float bv[4] = {0.f, 0.f, 0.f, 0.f};
    #pragma unroll
    for (int j = 0; j < 4; j++) {
        int c = bn + (tx << 2) + j;
        bv[j] = (c < Ncols) ? bias[c] : 0.f;
    }
    #pragma unroll
    for (int i = 0; i < 4; i++) {
        int r = bm + (ty << 2) + i;
        if (r >= M) continue;
        #pragma unroll
        for (int j = 0; j < 4; j++) {
            int c = bn + (tx << 2) + j;
            if (c >= Ncols) continue;
            C[(size_t)r * Ncols + c] = acc[i][j] + bv[j];
        }
    }
}

// ---------------- host orchestration: 2-stream overlap ----------------
extern "C" void kernel_launch(void* const* d_in, const int* in_sizes, int n_in,
                              void* d_out, int out_size) {
    const float* x     = (const float*)d_in[0];
    const int*   ei    = (const int*)  d_in[1];
    const float* ew    = (const float*)d_in[2];
    const float* h0    = (const float*)d_in[3];
    const float* linW  = (const float*)d_in[4];
    const float* linB  = (const float*)d_in[5];
    const float* convW = (const float*)d_in[6];
    const float* convB = (const float*)d_in[7];
    const float* Wih   = (const float*)d_in[8];
    const float* Whh   = (const float*)d_in[9];
    const float* bih   = (const float*)d_in[10];
    const float* bhh   = (const float*)d_in[11];
    const float* fcW   = (const float*)d_in[12];
    const float* fcB   = (const float*)d_in[13];
    float* out = (float*)d_out;

    const int* src = ei;
    const int* dst = ei + EE;

    static cudaStream_t s2 = nullptr;
    static cudaEvent_t evFork, evG0, evGru0, evA0, evR0, evA1, evA2, evEnd;
    static bool s_init_done = false;
    if (!s_init_done) {
        cudaFuncSetAttribute(gemm64_tf32_kernel<true, true>,
                             cudaFuncAttributeMaxDynamicSharedMemorySize, G64_SMEM_BYTES);
        cudaFuncSetAttribute(gemm64_tf32_kernel<false, false>,
                             cudaFuncAttributeMaxDynamicSharedMemorySize, G64_SMEM_BYTES);
        cudaFuncSetAttribute(gru_fused_kernel,
                             cudaFuncAttributeMaxDynamicSharedMemorySize, GRU_SMEM_BYTES);
        cudaStreamCreateWithFlags(&s2, cudaStreamNonBlocking);
        cudaEventCreateWithFlags(&evFork, cudaEventDisableTiming);
        cudaEventCreateWithFlags(&evG0,   cudaEventDisableTiming);
        cudaEventCreateWithFlags(&evGru0, cudaEventDisableTiming);
        cudaEventCreateWithFlags(&evA0,   cudaEventDisableTiming);
        cudaEventCreateWithFlags(&evR0,   cudaEventDisableTiming);
        cudaEventCreateWithFlags(&evA1,   cudaEventDisableTiming);
        cudaEventCreateWithFlags(&evA2,   cudaEventDisableTiming);
        cudaEventCreateWithFlags(&evEnd,  cudaEventDisableTiming);
        s_init_done = true;
    }

    float *p_xh1, *p_xh2, *p_xw, *p_h;
    cudaGetSymbolAddress((void**)&p_xh1, g_xh1);
    cudaGetSymbolAddress((void**)&p_xh2, g_xh2);
    cudaGetSymbolAddress((void**)&p_xw,  g_xw);
    cudaGetSymbolAddress((void**)&p_h,   g_h);

    const int EB = 256;
    const int NB = (NN + 127) / 128;       // 782
    const int NB64 = (NN + 63) / 64;       // 1563
    const dim3 blk256(256);
    const dim3 blk512(512);
    const dim3 g64_128(2, NB64);
    const int gatherBlocks = (NN * 32 + 255) / 256;

    const float* W0 = convW;
    const float* W1 = convW + (size_t)1 * FH * FH;
    const float* W2 = convW + (size_t)2 * FH * FH;
    const float* b0 = convB;
    const float* b1 = convB + FH;
    const float* b2 = convB + 2 * FH;

    // ---- fork: s2 branches off the capturing (legacy) stream ----
    cudaEventRecord(evFork, 0);
    cudaStreamWaitEvent(s2, evFork, 0);

    // ---- s2: lin -> G_0 -> GRU0 ----
    gemm64_tf32_kernel<true, true><<<g64_128, blk256, G64_SMEM_BYTES, s2>>>(
        x, linW, linB, p_xh1, NN, FH);
    gemm64_tf32_kernel<false, false><<<g64_128, blk256, G64_SMEM_BYTES, s2>>>(
        p_xh1, W0, nullptr, p_xw, NN, FH);
    cudaEventRecord(evG0, s2);
    gru_fused_kernel<<<NB, blk512, GRU_SMEM_BYTES, s2>>>(
        p_xh1, h0, Wih, Whh, bih, bhh, p_h, NN);
    cudaEventRecord(evGru0, s2);

    // ---- s0: CSR build (concurrent with lin/G_0/GRU0) ----
    init_deg_kernel<<<(NN + 255) / 256, 256>>>();
    accum_deg_kernel<<<(EE + EB - 1) / EB, EB>>>(dst, ew);
    dinv_kernel<<<(NN + 255) / 256, 256>>>();
    scan1_kernel<<<NBLK, SCAN_B>>>();
    scan2_kernel<<<1, 256>>>();
    scan3_kernel<<<(NN + 255) / 256, 256>>>();
    fill_kernel<<<(EE + EB - 1) / EB, EB>>>(src, dst, ew);

    // ---- s0: A_0 (needs CSR + G_0) ----
    cudaStreamWaitEvent(0, evG0, 0);
    gather_agg_kernel<<<gatherBlocks, 256>>>(p_xw, b0, p_xh2);
    cudaEventRecord(evA0, 0);

    // ---- s2: R_0 (needs A_0 + GRU0[in-order]) ----
    cudaStreamWaitEvent(s2, evA0, 0);
    gru_fused_kernel<<<NB, blk512, GRU_SMEM_BYTES, s2>>>(
        p_xh2, p_h, Wih, Whh, bih, bhh, p_h, NN);
    cudaEventRecord(evR0, s2);

    // ---- s0: G_1 -> A_1 (A_1 writes xh1: wait GRU0 reader) ----
    gemm64_tf32_kernel<false, false><<<g64_128, blk256, G64_SMEM_BYTES>>>(
        p_xh2, W1, nullptr, p_xw, NN, FH);
    cudaStreamWaitEvent(0, evGru0, 0);
    gather_agg_kernel<<<gatherBlocks, 256>>>(p_xw, b1, p_xh1);
    cudaEventRecord(evA1, 0);

    // ---- s2: R_1 (needs A_1 + R_0[in-order]) ----
    cudaStreamWaitEvent(s2, evA1, 0);
    gru_fused_kernel<<<NB, blk512, GRU_SMEM_BYTES, s2>>>(
        p_xh1, p_h, Wih, Whh, bih, bhh, p_h, NN);

    // ---- s0: G_2 -> A_2 (A_2 writes xh2: wait R_0 reader) ----
    gemm64_tf32_kernel<false, false><<<g64_128, blk256, G64_SMEM_BYTES>>>(
        p_xh1, W2, nullptr, p_xw, NN, FH);
    cudaStreamWaitEvent(0, evR0, 0);
    gather_agg_kernel<<<gatherBlocks, 256>>>(p_xw, b2, p_xh2);
    cudaEventRecord(evA2, 0);

    // ---- s2: R_2 -> fc ----
    cudaStreamWaitEvent(s2, evA2, 0);
    gru_fused_kernel<<<NB, blk512, GRU_SMEM_BYTES, s2>>>(
        p_xh2, p_h, Wih, Whh, bih, bhh, p_h, NN);
    {
        dim3 grid((CC + 63) / 64, (NN + 63) / 64);
        gemm_fc_kernel<<<grid, 256, 0, s2>>>(p_h, fcW, fcB, out, NN, CC);
    }
    cudaEventRecord(evEnd, s2);

    // ---- join back to the capturing stream ----
    cudaStreamWaitEvent(0, evEnd, 0);
}